// round 14
// baseline (speedup 1.0000x reference)
#include <cuda_runtime.h>
#include <cuda_fp16.h>
#include <stdint.h>
#include <math.h>

#define NN   8192
#define NE   500000
#define NREL 6
#define FEAT 256
#define HIDD 64
#define OUTD 128
#define MROW 4096   // SIZE
#define ITEM 8192
#define CB   8      // count blocks per relation
#define MHALF 2048

// ---------------- scratch (device globals: allocation-free) ----------------
__device__ int   g_outcnt[NREL][NN];
__device__ int   g_incnt [NREL][NN];
__device__ float g_outinv[NREL][NN];
__device__ float g_ininv [NREL][NN];
__device__ int   g_rowptr[NREL][NN + 1];
__device__ int   g_fill  [NREL][NN];
__device__ int   g_srcs  [NREL][NE];
__device__ __half g_xsh [NREL][NN * 64];    // layers 1-2 conv outputs (gathered)
__device__ float g_xs32 [NREL][NN * 128];   // layer-3 conv outputs (fp32, rows<4096)
__device__ float g_agg  [NREL][NN * 64];    // layer-3 pre-aggregated inputs
__device__ float g_node [3][NN * 128];      // trunk state fp32
__device__ __half g_nodeh[3][NN * 64];      // fp16 shadow for layer-3 gather

// pre-transposed fp16 weights
#define O1A 0                            // f1w top^T [256][8192]
#define O1B 2097152                      // f1w bot^T [256][128]
#define O2  2129920                      // f2w^T     [512][256]
#define O3  2260992                      // f3w^T     [1024][512]
#define O4  2785280                      // f4w^T     [8192][1024]
#define BT_TOTAL 11173888
__device__ __half g_bth[BT_TOTAL];

// fp16 activations
__device__ __half g_adjh[(size_t)MROW * ITEM];
__device__ __half g_feh[MROW * OUTD];
__device__ float  g_x1f[MROW * 256];        // f1 Adj-partial (fp32)
__device__ __half g_x1h[MROW * 256];
__device__ __half g_x2h[MROW * 512];
__device__ __half g_x3h[MROW * 1024];

// ---------------- fp16 helpers ----------------
__device__ __forceinline__ uint32_t pack_h2(float x, float y) {
    __half2 h = __floats2half2_rn(x, y);
    return *reinterpret_cast<uint32_t*>(&h);
}
__device__ __forceinline__ float4 h4tof4(uint2 u) {
    float2 a = __half22float2(*reinterpret_cast<__half2*>(&u.x));
    float2 b = __half22float2(*reinterpret_cast<__half2*>(&u.y));
    return make_float4(a.x, a.y, b.x, b.y);
}
__device__ __forceinline__ uint2 h2add(uint2 a, uint2 b) {
    __half2* A = reinterpret_cast<__half2*>(&a);
    __half2* B = reinterpret_cast<__half2*>(&b);
    uint2 r;
    reinterpret_cast<__half2*>(&r)[0] = __hadd2(A[0], B[0]);
    reinterpret_cast<__half2*>(&r)[1] = __hadd2(A[1], B[1]);
    return r;
}
__device__ __forceinline__ void store4(float* p, float a, float b, float c, float d) {
    *reinterpret_cast<float4*>(p) = make_float4(a, b, c, d);
}
__device__ __forceinline__ void store4(__half* p, float a, float b, float c, float d) {
    *reinterpret_cast<uint2*>(p) = make_uint2(pack_h2(a, b), pack_h2(c, d));
}

// ---------------- CSR build ----------------
__global__ void k_zero_counts() {
    int i = blockIdx.x * blockDim.x + threadIdx.x;
    if (i < NREL * NN) {
        ((int*)g_outcnt)[i] = 0;
        ((int*)g_incnt)[i]  = 0;
    }
}

__global__ void k_count(const int* __restrict__ edges) {
    extern __shared__ int smcnt[];            // [2*NN]
    const int r = blockIdx.y, b = blockIdx.x;
    int* so = smcnt;
    int* si = smcnt + NN;
    for (int i = threadIdx.x; i < 2 * NN; i += blockDim.x) smcnt[i] = 0;
    __syncthreads();
    const int per = NE / CB;
    const int e0 = b * per;
    const int* es = edges + (size_t)r * 2 * NE;
    for (int e = e0 + threadIdx.x * 4; e < e0 + per; e += blockDim.x * 4) {
        int4 s = *reinterpret_cast<const int4*>(es + e);
        int4 d = *reinterpret_cast<const int4*>(es + NE + e);
        atomicAdd(&so[s.x], 1); atomicAdd(&so[s.y], 1);
        atomicAdd(&so[s.z], 1); atomicAdd(&so[s.w], 1);
        atomicAdd(&si[d.x], 1); atomicAdd(&si[d.y], 1);
        atomicAdd(&si[d.z], 1); atomicAdd(&si[d.w], 1);
    }
    __syncthreads();
    for (int i = threadIdx.x; i < NN; i += blockDim.x) {
        int v = so[i];
        if (v) atomicAdd(&g_outcnt[r][i], v);
        v = si[i];
        if (v) atomicAdd(&g_incnt[r][i], v);
    }
}

__global__ void k_scan() {
    int r = blockIdx.x;
    int tid = threadIdx.x;          // 1024 threads
    int base = tid * 8;
    int c[8];
    int s = 0;
#pragma unroll
    for (int i = 0; i < 8; i++) { c[i] = g_incnt[r][base + i]; s += c[i]; }

    int lane = tid & 31, w = tid >> 5;
    int incl = s;
#pragma unroll
    for (int o = 1; o < 32; o <<= 1) {
        int v = __shfl_up_sync(0xffffffffu, incl, o);
        if (lane >= o) incl += v;
    }
    __shared__ int wsum[32];
    if (lane == 31) wsum[w] = incl;
    __syncthreads();
    if (w == 0) {
        int v = wsum[lane];
#pragma unroll
        for (int o = 1; o < 32; o <<= 1) {
            int t = __shfl_up_sync(0xffffffffu, v, o);
            if (lane >= o) v += t;
        }
        wsum[lane] = v;
    }
    __syncthreads();
    int excl = (incl - s) + (w > 0 ? wsum[w - 1] : 0);
    int run = excl;
#pragma unroll
    for (int i = 0; i < 8; i++) {
        g_rowptr[r][base + i] = run;
        g_fill[r][base + i]   = run;
        run += c[i];
        int ic = c[i] > 0 ? c[i] : 1;
        g_ininv[r][base + i] = rsqrtf((float)ic);
        int oc = g_outcnt[r][base + i];
        if (oc < 1) oc = 1;
        g_outinv[r][base + i] = rsqrtf((float)oc);
    }
    if (tid == 1023) g_rowptr[r][NN] = run;
}

__global__ void k_fill(const int* __restrict__ edges) {
    int i = (blockIdx.x * blockDim.x + threadIdx.x) * 4;
    if (i >= NREL * NE) return;
    int r = i / NE, e = i - r * NE;
    int4 src = *reinterpret_cast<const int4*>(edges + (size_t)r * 2 * NE + e);
    int4 dst = *reinterpret_cast<const int4*>(edges + (size_t)r * 2 * NE + NE + e);
    g_srcs[r][atomicAdd(&g_fill[r][dst.x], 1)] = src.x;
    g_srcs[r][atomicAdd(&g_fill[r][dst.y], 1)] = src.y;
    g_srcs[r][atomicAdd(&g_fill[r][dst.z], 1)] = src.z;
    g_srcs[r][atomicAdd(&g_fill[r][dst.w], 1)] = src.w;
}

// ---------------- conv GEMM batched over relations --------------------------
template <typename T>
__global__ void k_conv_b(const float* __restrict__ A0, const float* __restrict__ A1,
                         const float* __restrict__ A2, const float* __restrict__ Wb,
                         const float* __restrict__ scaleb, int K, int Nh,
                         T* __restrict__ xsbase, size_t xstride, uint32_t rpat) {
    const int r = (rpat >> (4 * blockIdx.z)) & 0xF;
    const int smap[6] = {0, 1, 0, 2, 2, 1};
    const float* A;
    if (A1 == nullptr) {
        A = A0 + (size_t)r * NN * K;
    } else {
        int si = smap[r];
        A = (si == 0) ? A0 : (si == 1) ? A1 : A2;
    }
    const float* W = Wb + (size_t)r * K * Nh;
    T* Xs = xsbase + (size_t)r * xstride;
    const float* scale = scaleb + r * NN;

    __shared__ float As[16][64];
    __shared__ float Bs[16][64];
    int tid = threadIdx.x;
    int bx = blockIdx.x, by = blockIdx.y;
    int aRow = tid >> 2, aCol = (tid & 3) * 4;
    int bRow = tid >> 4, bCol = (tid & 15) * 4;
    int tx = tid & 15, ty = tid >> 4;
    float acc[4][4] = {};
    const float* Ap = A + (size_t)(by * 64) * K;
    float scl = scale[by * 64 + aRow];

    for (int k0 = 0; k0 < K; k0 += 16) {
        float4 av = *(const float4*)(Ap + (size_t)aRow * K + k0 + aCol);
        As[aCol + 0][aRow] = av.x * scl;
        As[aCol + 1][aRow] = av.y * scl;
        As[aCol + 2][aRow] = av.z * scl;
        As[aCol + 3][aRow] = av.w * scl;
        float4 bv = *(const float4*)(W + (size_t)(k0 + bRow) * Nh + bx * 64 + bCol);
        *(float4*)&Bs[bRow][bCol] = bv;
        __syncthreads();
#pragma unroll
        for (int kk = 0; kk < 16; kk++) {
            float a[4], b[4];
#pragma unroll
            for (int i = 0; i < 4; i++) a[i] = As[kk][ty * 4 + i];
#pragma unroll
            for (int j = 0; j < 4; j++) b[j] = Bs[kk][tx * 4 + j];
#pragma unroll
            for (int i = 0; i < 4; i++)
#pragma unroll
                for (int j = 0; j < 4; j++) acc[i][j] += a[i] * b[j];
        }
        __syncthreads();
    }
    int row0 = by * 64 + ty * 4, col0 = bx * 64 + tx * 4;
#pragma unroll
    for (int i = 0; i < 4; i++)
        store4(Xs + (size_t)(row0 + i) * Nh + col0,
               acc[i][0], acc[i][1], acc[i][2], acc[i][3]);
}

// ---------------- aggregation helpers ----------------
__device__ __forceinline__ float4 f4add(float4 a, float4 b) {
    a.x += b.x; a.y += b.y; a.z += b.z; a.w += b.w; return a;
}
__device__ __forceinline__ float4 f4fma(float4 a, float s, float4 acc) {
    acc.x += a.x * s; acc.y += a.y * s; acc.z += a.z * s; acc.w += a.w * s; return acc;
}

// post-GEMM agg: both relations interleaved
__global__ void k_agg_v(const float* __restrict__ bias, int tbase) {
    const int t = tbase + blockIdx.y;
    const int n = blockIdx.x * blockDim.y + threadIdx.y;
    const int lane = threadIdx.x;     // 0..15
    const int RA[3] = {1, 0, 2};
    const int RB[3] = {3, 4, 5};
    const int r0 = RA[t], r1 = RB[t];
    const __half* xa = g_xsh[r0];
    const __half* xb = g_xsh[r1];
    const int* sa_ = g_srcs[r0];
    const int* sb_ = g_srcs[r1];
    int ea = g_rowptr[r0][n], ea1 = g_rowptr[r0][n + 1];
    int eb = g_rowptr[r1][n], eb1 = g_rowptr[r1][n + 1];
    float4 sA = make_float4(0.f, 0.f, 0.f, 0.f);
    float4 sB = make_float4(0.f, 0.f, 0.f, 0.f);

    while (ea + 7 < ea1 && eb + 7 < eb1) {
        uint2 a0 = reinterpret_cast<const uint2*>(xa + (size_t)sa_[ea] * 64)[lane];
        uint2 a1 = reinterpret_cast<const uint2*>(xa + (size_t)sa_[ea + 1] * 64)[lane];
        uint2 a2 = reinterpret_cast<const uint2*>(xa + (size_t)sa_[ea + 2] * 64)[lane];
        uint2 a3 = reinterpret_cast<const uint2*>(xa + (size_t)sa_[ea + 3] * 64)[lane];
        uint2 a4 = reinterpret_cast<const uint2*>(xa + (size_t)sa_[ea + 4] * 64)[lane];
        uint2 a5 = reinterpret_cast<const uint2*>(xa + (size_t)sa_[ea + 5] * 64)[lane];
        uint2 a6 = reinterpret_cast<const uint2*>(xa + (size_t)sa_[ea + 6] * 64)[lane];
        uint2 a7 = reinterpret_cast<const uint2*>(xa + (size_t)sa_[ea + 7] * 64)[lane];
        uint2 b0 = reinterpret_cast<const uint2*>(xb + (size_t)sb_[eb] * 64)[lane];
        uint2 b1 = reinterpret_cast<const uint2*>(xb + (size_t)sb_[eb + 1] * 64)[lane];
        uint2 b2 = reinterpret_cast<const uint2*>(xb + (size_t)sb_[eb + 2] * 64)[lane];
        uint2 b3 = reinterpret_cast<const uint2*>(xb + (size_t)sb_[eb + 3] * 64)[lane];
        uint2 b4 = reinterpret_cast<const uint2*>(xb + (size_t)sb_[eb + 4] * 64)[lane];
        uint2 b5 = reinterpret_cast<const uint2*>(xb + (size_t)sb_[eb + 5] * 64)[lane];
        uint2 b6 = reinterpret_cast<const uint2*>(xb + (size_t)sb_[eb + 6] * 64)[lane];
        uint2 b7 = reinterpret_cast<const uint2*>(xb + (size_t)sb_[eb + 7] * 64)[lane];
        float4 pa0 = h4tof4(h2add(a0, a1));
        float4 pa1 = h4tof4(h2add(a2, a3));
        float4 pa2 = h4tof4(h2add(a4, a5));
        float4 pa3 = h4tof4(h2add(a6, a7));
        float4 pb0 = h4tof4(h2add(b0, b1));
        float4 pb1 = h4tof4(h2add(b2, b3));
        float4 pb2 = h4tof4(h2add(b4, b5));
        float4 pb3 = h4tof4(h2add(b6, b7));
        sA = f4add(sA, f4add(f4add(pa0, pa1), f4add(pa2, pa3)));
        sB = f4add(sB, f4add(f4add(pb0, pb1), f4add(pb2, pb3)));
        ea += 8; eb += 8;
    }
    for (; ea + 7 < ea1; ea += 8) {
        uint2 a0 = reinterpret_cast<const uint2*>(xa + (size_t)sa_[ea] * 64)[lane];
        uint2 a1 = reinterpret_cast<const uint2*>(xa + (size_t)sa_[ea + 1] * 64)[lane];
        uint2 a2 = reinterpret_cast<const uint2*>(xa + (size_t)sa_[ea + 2] * 64)[lane];
        uint2 a3 = reinterpret_cast<const uint2*>(xa + (size_t)sa_[ea + 3] * 64)[lane];
        uint2 a4 = reinterpret_cast<const uint2*>(xa + (size_t)sa_[ea + 4] * 64)[lane];
        uint2 a5 = reinterpret_cast<const uint2*>(xa + (size_t)sa_[ea + 5] * 64)[lane];
        uint2 a6 = reinterpret_cast<const uint2*>(xa + (size_t)sa_[ea + 6] * 64)[lane];
        uint2 a7 = reinterpret_cast<const uint2*>(xa + (size_t)sa_[ea + 7] * 64)[lane];
        float4 p0 = h4tof4(h2add(a0, a1));
        float4 p1 = h4tof4(h2add(a2, a3));
        float4 p2 = h4tof4(h2add(a4, a5));
        float4 p3 = h4tof4(h2add(a6, a7));
        sA = f4add(sA, f4add(f4add(p0, p1), f4add(p2, p3)));
    }
    for (; ea < ea1; ea++)
        sA = f4add(sA, h4tof4(reinterpret_cast<const uint2*>(xa + (size_t)sa_[ea] * 64)[lane]));
    for (; eb + 7 < eb1; eb += 8) {
        uint2 b0 = reinterpret_cast<const uint2*>(xb + (size_t)sb_[eb] * 64)[lane];
        uint2 b1 = reinterpret_cast<const uint2*>(xb + (size_t)sb_[eb + 1] * 64)[lane];
        uint2 b2 = reinterpret_cast<const uint2*>(xb + (size_t)sb_[eb + 2] * 64)[lane];
        uint2 b3 = reinterpret_cast<const uint2*>(xb + (size_t)sb_[eb + 3] * 64)[lane];
        uint2 b4 = reinterpret_cast<const uint2*>(xb + (size_t)sb_[eb + 4] * 64)[lane];
        uint2 b5 = reinterpret_cast<const uint2*>(xb + (size_t)sb_[eb + 5] * 64)[lane];
        uint2 b6 = reinterpret_cast<const uint2*>(xb + (size_t)sb_[eb + 6] * 64)[lane];
        uint2 b7 = reinterpret_cast<const uint2*>(xb + (size_t)sb_[eb + 7] * 64)[lane];
        float4 p0 = h4tof4(h2add(b0, b1));
        float4 p1 = h4tof4(h2add(b2, b3));
        float4 p2 = h4tof4(h2add(b4, b5));
        float4 p3 = h4tof4(h2add(b6, b7));
        sB = f4add(sB, f4add(f4add(p0, p1), f4add(p2, p3)));
    }
    for (; eb < eb1; eb++)
        sB = f4add(sB, h4tof4(reinterpret_cast<const uint2*>(xb + (size_t)sb_[eb] * 64)[lane]));

    float4 acc = f4add(reinterpret_cast<const float4*>(bias + r0 * 64)[lane],
                       reinterpret_cast<const float4*>(bias + r1 * 64)[lane]);
    acc = f4fma(sA, g_ininv[r0][n], acc);
    acc = f4fma(sB, g_ininv[r1][n], acc);
    reinterpret_cast<float4*>(g_node[t] + (size_t)n * 64)[lane] = acc;
    reinterpret_cast<uint2*>(g_nodeh[t] + (size_t)n * 64)[lane] =
        make_uint2(pack_h2(acc.x, acc.y), pack_h2(acc.z, acc.w));
}

// pre-GEMM agg (layer 3): relations {1,3}, dst rows [0,4096) only
__global__ void k_aggpre() {
    const int r = 1 + 2 * blockIdx.y;           // 1, 3
    const int n = blockIdx.x * blockDim.y + threadIdx.y;   // < 4096
    const int lane = threadIdx.x;     // 0..15
    const int smap[6] = {0, 1, 0, 2, 2, 1};
    const __half* x = g_nodeh[smap[r]];
    const float* oi = g_outinv[r];
    const int* srcs = g_srcs[r];
    int e0 = g_rowptr[r][n], e1 = g_rowptr[r][n + 1];
    float4 acc = make_float4(0.f, 0.f, 0.f, 0.f);
    int e = e0;
    for (; e + 7 < e1; e += 8) {
        int s0 = srcs[e], s1 = srcs[e + 1], s2 = srcs[e + 2], s3 = srcs[e + 3];
        int s4 = srcs[e + 4], s5 = srcs[e + 5], s6 = srcs[e + 6], s7 = srcs[e + 7];
        uint2 u0 = reinterpret_cast<const uint2*>(x + (size_t)s0 * 64)[lane];
        uint2 u1 = reinterpret_cast<const uint2*>(x + (size_t)s1 * 64)[lane];
        uint2 u2 = reinterpret_cast<const uint2*>(x + (size_t)s2 * 64)[lane];
        uint2 u3 = reinterpret_cast<const uint2*>(x + (size_t)s3 * 64)[lane];
        uint2 u4 = reinterpret_cast<const uint2*>(x + (size_t)s4 * 64)[lane];
        uint2 u5 = reinterpret_cast<const uint2*>(x + (size_t)s5 * 64)[lane];
        uint2 u6 = reinterpret_cast<const uint2*>(x + (size_t)s6 * 64)[lane];
        uint2 u7 = reinterpret_cast<const uint2*>(x + (size_t)s7 * 64)[lane];
        acc = f4fma(h4tof4(u0), oi[s0], acc);
        acc = f4fma(h4tof4(u1), oi[s1], acc);
        acc = f4fma(h4tof4(u2), oi[s2], acc);
        acc = f4fma(h4tof4(u3), oi[s3], acc);
        acc = f4fma(h4tof4(u4), oi[s4], acc);
        acc = f4fma(h4tof4(u5), oi[s5], acc);
        acc = f4fma(h4tof4(u6), oi[s6], acc);
        acc = f4fma(h4tof4(u7), oi[s7], acc);
    }
    for (; e < e1; e++) {
        int s0 = srcs[e];
        uint2 u0 = reinterpret_cast<const uint2*>(x + (size_t)s0 * 64)[lane];
        acc = f4fma(h4tof4(u0), oi[s0], acc);
    }
    reinterpret_cast<float4*>(g_agg[r] + (size_t)n * 64)[lane] = acc;
}

// ---------------- fused combine + L1-normalize (rows [0,4096)) -------------
__global__ void k_l1norm(const float* __restrict__ b3,
                         float* __restrict__ out, __half* __restrict__ feh) {
    int row = blockIdx.x;
    int h = threadIdx.x;  // 128
    float v = g_xs32[1][(size_t)row * OUTD + h] + g_xs32[3][(size_t)row * OUTD + h]
            + b3[128 + h] + b3[384 + h];
    float a = fabsf(v);
#pragma unroll
    for (int o = 16; o > 0; o >>= 1) a += __shfl_xor_sync(0xffffffffu, a, o);
    __shared__ float sh[4];
    if ((h & 31) == 0) sh[h >> 5] = a;
    __syncthreads();
    float tot = sh[0] + sh[1] + sh[2] + sh[3];
    float r = v / fmaxf(tot, 1e-12f);
    out[(size_t)row * OUTD + h] = r;
    feh[(size_t)row * OUTD + h] = __float2half_rn(r);
}

// ---------------- Adj fp32 -> fp16 -----------------------------------------
__global__ void k_cvt(const float4* __restrict__ src, __half* __restrict__ dst) {
    size_t i = (size_t)blockIdx.x * blockDim.x + threadIdx.x;
    float4 v = src[i];
    uint2 p = make_uint2(pack_h2(v.x, v.y), pack_h2(v.z, v.w));
    *reinterpret_cast<uint2*>(dst + 4 * i) = p;
}

// ---------------- weight transpose fp16: B[K][N] -> Bt[N][K] ---------------
__global__ void k_tsp(const float* __restrict__ B, __half* __restrict__ th,
                      int K, int N) {
    __shared__ float s[32][33];
    int n0 = blockIdx.x * 32, k0 = blockIdx.y * 32;
    int tx = threadIdx.x, ty = threadIdx.y;
#pragma unroll
    for (int i = 0; i < 32; i += 8)
        s[ty + i][tx] = B[(size_t)(k0 + ty + i) * N + n0 + tx];
    __syncthreads();
#pragma unroll
    for (int i = 0; i < 32; i += 8) {
        int n = n0 + ty + i, k = k0 + tx;
        th[(size_t)n * K + k] = __float2half_rn(s[tx][ty + i]);
    }
}

// ---------------- mma.sync + ldmatrix + cp.async plumbing ------------------
__device__ __forceinline__ uint32_t s2u(const void* p) {
    uint32_t a;
    asm("{ .reg .u64 t; cvta.to.shared.u64 t, %1; cvt.u32.u64 %0, t; }" : "=r"(a) : "l"(p));
    return a;
}
__device__ __forceinline__ void mma_f16(float* d, const uint32_t* a, const uint32_t* b) {
    asm volatile(
        "mma.sync.aligned.m16n8k16.row.col.f32.f16.f16.f32 "
        "{%0,%1,%2,%3}, {%4,%5,%6,%7}, {%8,%9}, {%0,%1,%2,%3};"
        : "+f"(d[0]), "+f"(d[1]), "+f"(d[2]), "+f"(d[3])
        : "r"(a[0]), "r"(a[1]), "r"(a[2]), "r"(a[3]), "r"(b[0]), "r"(b[1]));
}
__device__ __forceinline__ void ldsm4(uint32_t* r, uint32_t addr) {
    asm volatile("ldmatrix.sync.aligned.m8n8.x4.shared.b16 {%0,%1,%2,%3}, [%4];"
                 : "=r"(r[0]), "=r"(r[1]), "=r"(r[2]), "=r"(r[3]) : "r"(addr));
}
__device__ __forceinline__ void cpa16(uint32_t s, const void* g) {
    asm volatile("cp.async.cg.shared.global [%0], [%1], 16;" :: "r"(s), "l"(g));
}
#define CP_COMMIT() asm volatile("cp.async.commit_group;" ::: "memory")
#define CP_WAIT2()  asm volatile("cp.async.wait_group 2;" ::: "memory")

// ---------------- MLP GEMM: fp16 single-pass, templated BN -----------------
template <int ACT, int OUT, bool HC, int NT>
__global__ void __launch_bounds__(256, 1)
k_tc(const __half* __restrict__ A_, const __half* __restrict__ Bh_,
     const float* __restrict__ bias, const float* __restrict__ Cin,
     float* __restrict__ Cf, __half* __restrict__ Oh, int N, int K) {
    constexpr int BN = NT * 16;
    constexpr uint32_t ASZ = 16384u;
    constexpr uint32_t STG = ASZ + (uint32_t)BN * 128u;
    extern __shared__ char smc[];
    const uint32_t sb = s2u(smc);
    const int tid = threadIdx.x, lane = tid & 31, warp = tid >> 5;
    const int wm = warp & 3, wn = warp >> 2;
    const int g = lane >> 2, tig = lane & 3;
    const int bm = blockIdx.y * 128, bn = blockIdx.x * BN;

    float c[2][NT][4];
#pragma unroll
    for (int i = 0; i < 2; i++)
#pragma unroll
        for (int j = 0; j < NT; j++)
#pragma unroll
            for (int q = 0; q < 4; q++) c[i][j][q] = 0.f;

    auto load_stage = [&](int s) {
        const uint32_t st = sb + (uint32_t)(s % 3) * STG;
        const int k0 = s * 64;
#pragma unroll
        for (int j = 0; j < (128 + BN) / 32; j++) {
            int cidx = tid + 256 * j;
            int row = cidx >> 3, kc = cidx & 7;
            if (row < 128) {
                uint32_t off = (uint32_t)(row * 128 + kc * 16);
                off ^= (off >> 3) & 0x70;
                cpa16(st + off, A_ + (size_t)(bm + row) * K + k0 + kc * 8);
            } else {
                int br = row - 128;
                uint32_t off = (uint32_t)(br * 128 + kc * 16);
                off ^= (off >> 3) & 0x70;
                cpa16(st + ASZ + off, Bh_ + (size_t)(bn + br) * K + k0 + kc * 8);
            }
        }
    };

    const int nst = K >> 6;
#pragma unroll
    for (int i = 0; i < 3; i++) {
        if (i < nst) load_stage(i);
        CP_COMMIT();
    }

    for (int s = 0; s < nst; s++) {
        CP_WAIT2();
        __syncthreads();
        const uint32_t st = sb + (uint32_t)(s % 3) * STG;
#pragma unroll
        for (int kk = 0; kk < 64; kk += 16) {
            uint32_t ah[2][4], bh[NT][2];
#pragma unroll
            for (int mt = 0; mt < 2; mt++) {
                int row = wm * 32 + mt * 16 + (lane & 15);
                uint32_t off = (uint32_t)(row * 128) + (uint32_t)(kk * 2) + (uint32_t)(lane & 16);
                off ^= (off >> 3) & 0x70;
                ldsm4(ah[mt], st + off);
            }
#pragma unroll
            for (int bt = 0; bt < NT / 2; bt++) {
                int row = wn * (8 * NT) + bt * 16 + ((lane >> 4) << 3) + (lane & 7);
                uint32_t off = (uint32_t)(row * 128) + (uint32_t)(kk * 2) + (uint32_t)((lane & 8) << 1);
                off ^= (off >> 3) & 0x70;
                uint32_t r[4];
                ldsm4(r, st + ASZ + off);
                bh[2 * bt][0] = r[0]; bh[2 * bt][1] = r[1];
                bh[2 * bt + 1][0] = r[2]; bh[2 * bt + 1][1] = r[3];
            }
#pragma unroll
            for (int mt = 0; mt < 2; mt++)
#pragma unroll
                for (int nt = 0; nt < NT; nt++)
                    mma_f16(c[mt][nt], ah[mt], bh[nt]);
        }
        __syncthreads();
        if (s + 3 < nst) load_stage(s + 3);
        CP_COMMIT();
    }

    // epilogue
#pragma unroll
    for (int mt = 0; mt < 2; mt++) {
#pragma unroll
        for (int nt = 0; nt < NT; nt++) {
            int m0 = bm + wm * 32 + mt * 16 + g;
            int n0 = bn + wn * (8 * NT) + nt * 8 + 2 * tig;
            float2 v0 = make_float2(c[mt][nt][0], c[mt][nt][1]);
            float2 v1 = make_float2(c[mt][nt][2], c[mt][nt][3]);
            if (HC) {
                float2 ci0 = *reinterpret_cast<const float2*>(Cin + (size_t)m0 * N + n0);
                float2 ci1 = *reinterpret_cast<const float2*>(Cin + (size_t)(m0 + 8) * N + n0);
                v0.x += ci0.x; v0.y += ci0.y; v1.x += ci1.x; v1.y += ci1.y;
            }
            if (bias) {
                float bx = bias[n0], by = bias[n0 + 1];
                v0.x += bx; v0.y += by; v1.x += bx; v1.y += by;
            }
            if (ACT == 1) {
                v0.x = fmaxf(v0.x, 0.f); v0.y = fmaxf(v0.y, 0.f);
                v1.x = fmaxf(v1.x, 0.f); v1.y = fmaxf(v1.y, 0.f);
            } else if (ACT == 2) {
                v0.x = 1.f / (1.f + expf(-v0.x)); v0.y = 1.f / (1.f + expf(-v0.y));
                v1.x = 1.f / (1.f + expf(-v1.x)); v1.y = 1.f / (1.f + expf(-v1.y));
            }
            if (OUT == 0) {
                *reinterpret_cast<float2*>(Cf + (size_t)m0 * N + n0) = v0;
                *reinterpret_cast<float2*>(Cf + (size_t)(m0 + 8) * N + n0) = v1;
            } else {
                *reinterpret_cast<uint32_t*>(Oh + (size_t)m0 * N + n0) = pack_h2(v0.x, v0.y);
                *reinterpret_cast<uint32_t*>(Oh + (size_t)(m0 + 8) * N + n0) = pack_h2(v1.x, v1.y);
            }
        }
    }
}

#define SM8  (3 * (16384 + 128 * 128))   // 96 KB  (NT=8)
#define SM16 (3 * (16384 + 256 * 128))   // 144 KB (NT=16)

// ---------------- orchestration ----------------
extern "C" void kernel_launch(void* const* d_in, const int* in_sizes, int n_in,
                              void* d_out, int out_size) {
    const float* hM  = (const float*)d_in[0];
    const float* hD  = (const float*)d_in[1];
    const float* hT  = (const float*)d_in[2];
    const float* W1  = (const float*)d_in[3];
    const float* b1  = (const float*)d_in[4];
    const float* W2  = (const float*)d_in[5];
    const float* b2  = (const float*)d_in[6];
    const float* W3  = (const float*)d_in[7];
    const float* b3  = (const float*)d_in[8];
    const float* Adj = (const float*)d_in[9];
    const float* f1w = (const float*)d_in[10];
    const float* f1b = (const float*)d_in[11];
    const float* f2w = (const float*)d_in[12];
    const float* f2b = (const float*)d_in[13];
    const float* f3w = (const float*)d_in[14];
    const float* f3b = (const float*)d_in[15];
    const float* f4w = (const float*)d_in[16];
    const float* f4b = (const float*)d_in[17];
    const int* edges = (const int*)d_in[18];

    float *p_node, *p_agg, *p_outinv, *p_ininv, *p_xs32, *p_x1f;
    __half *p_bth, *p_adjh, *p_feh, *p_x1h, *p_x2h, *p_x3h, *p_xsh;
    cudaGetSymbolAddress((void**)&p_node, g_node);
    cudaGetSymbolAddress((void**)&p_agg, g_agg);
    cudaGetSymbolAddress((void**)&p_outinv, g_outinv);
    cudaGetSymbolAddress((void**)&p_ininv, g_ininv);
    cudaGetSymbolAddress((void**)&p_xs32, g_xs32);
    cudaGetSymbolAddress((void**)&p_xsh, g_xsh);
    cudaGetSymbolAddress((void**)&p_bth, g_bth);
    cudaGetSymbolAddress((void**)&p_adjh, g_adjh);
    cudaGetSymbolAddress((void**)&p_feh, g_feh);
    cudaGetSymbolAddress((void**)&p_x1f, g_x1f);
    cudaGetSymbolAddress((void**)&p_x1h, g_x1h);
    cudaGetSymbolAddress((void**)&p_x2h, g_x2h);
    cudaGetSymbolAddress((void**)&p_x3h, g_x3h);

    float* fe   = (float*)d_out;                       // 4096 x 128
    float* outx = (float*)d_out + (size_t)MROW * OUTD; // 4096 x 8192

    static cudaStream_t s2 = nullptr, s3 = nullptr;
    static cudaEvent_t evFork = nullptr, evJoin = nullptr, evScan = nullptr, evFill = nullptr;
    static cudaEvent_t evX1 = nullptr, evB3 = nullptr;
    if (s2 == nullptr) {
        cudaStreamCreateWithFlags(&s2, cudaStreamNonBlocking);
        cudaStreamCreateWithFlags(&s3, cudaStreamNonBlocking);
        cudaEventCreateWithFlags(&evFork, cudaEventDisableTiming);
        cudaEventCreateWithFlags(&evJoin, cudaEventDisableTiming);
        cudaEventCreateWithFlags(&evScan, cudaEventDisableTiming);
        cudaEventCreateWithFlags(&evFill, cudaEventDisableTiming);
        cudaEventCreateWithFlags(&evX1, cudaEventDisableTiming);
        cudaEventCreateWithFlags(&evB3, cudaEventDisableTiming);
        cudaFuncSetAttribute(k_tc<0, 0, false, 8>, cudaFuncAttributeMaxDynamicSharedMemorySize, SM8);
        cudaFuncSetAttribute(k_tc<1, 1, true, 8>,  cudaFuncAttributeMaxDynamicSharedMemorySize, SM8);
        cudaFuncSetAttribute(k_tc<1, 1, false, 8>, cudaFuncAttributeMaxDynamicSharedMemorySize, SM8);
        cudaFuncSetAttribute(k_tc<2, 0, false, 16>, cudaFuncAttributeMaxDynamicSharedMemorySize, SM16);
        cudaFuncSetAttribute(k_count, cudaFuncAttributeMaxDynamicSharedMemorySize, 2 * NN * 4);
    }

    // ---- fork s2: MLP prep + Adj GEMM (independent of GNN) ----
    cudaEventRecord(evFork, 0);
    cudaStreamWaitEvent(s2, evFork, 0);
    k_cvt<<<(MROW * ITEM / 4) / 256, 256, 0, s2>>>((const float4*)Adj, p_adjh);
    k_tsp<<<dim3(256 / 32, 8192 / 32), dim3(32, 8), 0, s2>>>(f1w, p_bth + O1A, 8192, 256);
    k_tsp<<<dim3(256 / 32, 128 / 32),  dim3(32, 8), 0, s2>>>(f1w + (size_t)ITEM * 256, p_bth + O1B, 128, 256);
    k_tsp<<<dim3(512 / 32, 256 / 32),  dim3(32, 8), 0, s2>>>(f2w, p_bth + O2, 256, 512);
    k_tsp<<<dim3(1024 / 32, 512 / 32), dim3(32, 8), 0, s2>>>(f3w, p_bth + O3, 512, 1024);
    k_tsp<<<dim3(8192 / 32, 1024 / 32), dim3(32, 8), 0, s2>>>(f4w, p_bth + O4, 1024, 8192);
    k_tc<0, 0, false, 8><<<dim3(2, 32), 256, SM8, s2>>>(
        p_adjh, p_bth + O1A, nullptr, nullptr, p_x1f, nullptr, 256, 8192);
    cudaEventRecord(evJoin, s2);

    // ---- main stream: CSR counts + scan ----
    k_zero_counts<<<(NREL * NN + 255) / 256, 256>>>();
    k_count<<<dim3(CB, NREL), 512, 2 * NN * 4>>>(edges);
    k_scan<<<NREL, 1024>>>();
    cudaEventRecord(evScan, 0);

    // ---- fork s3: CSR fill ----
    cudaStreamWaitEvent(s3, evScan, 0);
    k_fill<<<(NREL * NE / 4 + 255) / 256, 256, 0, s3>>>(edges);
    cudaEventRecord(evFill, s3);

    // ---- main: layer-1 conv overlaps fill ----
    k_conv_b<__half><<<dim3(1, NN / 64, 6), 256>>>(hM, hD, hT, W1, p_outinv, 256, 64,
                                                   p_xsh, (size_t)NN * 64, 0x543210u);
    cudaStreamWaitEvent(0, evFill, 0);
    k_agg_v<<<dim3(NN / 16, 3), dim3(16, 16)>>>(b1, 0);

    // layer 2: relations {0,2,4,5}, targets {D,T}
    k_conv_b<__half><<<dim3(1, NN / 64, 4), 256>>>(p_node, p_node + (size_t)NN * 128,
                                                   p_node + (size_t)2 * NN * 128, W2,
                                                   p_outinv, 64, 64, p_xsh, (size_t)NN * 64,
                                                   0x5420u);
    k_agg_v<<<dim3(NN / 16, 2), dim3(16, 16)>>>(b2, 1);

    // layer 3: relations {1,3}, dst rows [0,4096) only
    k_aggpre<<<dim3(MROW / 16, 2), dim3(16, 16)>>>();
    k_conv_b<float><<<dim3(2, MROW / 64, 2), 256>>>(p_agg, nullptr, nullptr, W3, p_ininv,
                                                    64, 128, p_xs32, (size_t)NN * 128, 0x31u);
    k_l1norm<<<MROW, 128>>>(b3, fe, p_feh);

    // ---- join + MLP tail (M-split pipelined across main and s2) ----
    cudaStreamWaitEvent(0, evJoin, 0);

    // f1b: full M (tiny)
    k_tc<1, 1, true, 8><<<dim3(2, 32), 256, SM8>>>(
        p_feh, p_bth + O1B, f1b, p_x1f, nullptr, p_x1h, 256, 128);
    cudaEventRecord(evX1, 0);

    // half A (rows 0..2047) on main
    k_tc<1, 1, false, 8><<<dim3(4, MHALF / 128), 256, SM8>>>(
        p_x1h, p_bth + O2, f2b, nullptr, nullptr, p_x2h, 512, 256);
    k_tc<1, 1, false, 8><<<dim3(8, MHALF / 128), 256, SM8>>>(
        p_x2h, p_bth + O3, f3b, nullptr, nullptr, p_x3h, 1024, 512);

    // half B (rows 2048..4095) on s2, concurrent with main's f3a/f4a
    cudaStreamWaitEvent(s2, evX1, 0);
    k_tc<1, 1, false, 8><<<dim3(4, MHALF / 128), 256, SM8, s2>>>(
        p_x1h + (size_t)MHALF * 256, p_bth + O2, f2b, nullptr, nullptr,
        p_x2h + (size_t)MHALF * 512, 512, 256);
    k_tc<1, 1, false, 8><<<dim3(8, MHALF / 128), 256, SM8, s2>>>(
        p_x2h + (size_t)MHALF * 512, p_bth + O3, f3b, nullptr, nullptr,
        p_x3h + (size_t)MHALF * 1024, 1024, 512);
    cudaEventRecord(evB3, s2);

    // f4 half A on main (overlaps s2's f2b/f3b)
    k_tc<2, 0, false, 16><<<dim3(32, MHALF / 128), 256, SM16>>>(
        p_x3h, p_bth + O4, f4b, nullptr, outx, nullptr, 8192, 1024);

    // f4 half B after s2 finishes x3 rows 2048+
    cudaStreamWaitEvent(0, evB3, 0);
    k_tc<2, 0, false, 16><<<dim3(32, MHALF / 128), 256, SM16>>>(
        p_x3h + (size_t)MHALF * 1024, p_bth + O4, f4b, nullptr,
        outx + (size_t)MHALF * 8192, nullptr, 8192, 1024);
}

// round 15
// speedup vs baseline: 1.0581x; 1.0581x over previous
#include <cuda_runtime.h>
#include <cuda_fp16.h>
#include <stdint.h>
#include <math.h>

#define NN   8192
#define NE   500000
#define NREL 6
#define FEAT 256
#define HIDD 64
#define OUTD 128
#define MROW 4096   // SIZE
#define ITEM 8192
#define CB   8      // count blocks per relation

// ---------------- scratch (device globals: allocation-free) ----------------
__device__ int   g_outcnt[NREL][NN];
__device__ int   g_incnt [NREL][NN];
__device__ float g_outinv[NREL][NN];
__device__ float g_ininv [NREL][NN];
__device__ int   g_rowptr[NREL][NN + 1];
__device__ int   g_fill  [NREL][NN];
__device__ int   g_srcs  [NREL][NE];
__device__ __half g_xsh [NREL][NN * 64];    // layers 1-2 conv outputs (gathered)
__device__ float g_xs32 [NREL][NN * 128];   // layer-3 conv outputs (fp32, rows<4096)
__device__ float g_agg  [NREL][NN * 64];    // layer-3 pre-aggregated inputs
__device__ float g_node [3][NN * 128];      // trunk state fp32
__device__ __half g_nodeh[3][NN * 64];      // fp16 shadow for layer-3 gather

// pre-transposed fp16 weights
#define O1A 0                            // f1w top^T [256][8192]
#define O1B 2097152                      // f1w bot^T [256][128]
#define O2  2129920                      // f2w^T     [512][256]
#define O3  2260992                      // f3w^T     [1024][512]
#define O4  2785280                      // f4w^T     [8192][1024]
#define BT_TOTAL 11173888
__device__ __half g_bth[BT_TOTAL];

// fp16 activations
__device__ __half g_adjh[(size_t)MROW * ITEM];
__device__ __half g_feh[MROW * OUTD];
__device__ float  g_x1f[MROW * 256];        // f1 Adj-partial (fp32)
__device__ __half g_x1h[MROW * 256];
__device__ __half g_x2h[MROW * 512];
__device__ __half g_x3h[MROW * 1024];

// ---------------- fp16 helpers ----------------
__device__ __forceinline__ uint32_t pack_h2(float x, float y) {
    __half2 h = __floats2half2_rn(x, y);
    return *reinterpret_cast<uint32_t*>(&h);
}
__device__ __forceinline__ float4 h4tof4(uint2 u) {
    float2 a = __half22float2(*reinterpret_cast<__half2*>(&u.x));
    float2 b = __half22float2(*reinterpret_cast<__half2*>(&u.y));
    return make_float4(a.x, a.y, b.x, b.y);
}
__device__ __forceinline__ uint2 h2add(uint2 a, uint2 b) {
    __half2* A = reinterpret_cast<__half2*>(&a);
    __half2* B = reinterpret_cast<__half2*>(&b);
    uint2 r;
    reinterpret_cast<__half2*>(&r)[0] = __hadd2(A[0], B[0]);
    reinterpret_cast<__half2*>(&r)[1] = __hadd2(A[1], B[1]);
    return r;
}
__device__ __forceinline__ void store4(float* p, float a, float b, float c, float d) {
    *reinterpret_cast<float4*>(p) = make_float4(a, b, c, d);
}
__device__ __forceinline__ void store4(__half* p, float a, float b, float c, float d) {
    *reinterpret_cast<uint2*>(p) = make_uint2(pack_h2(a, b), pack_h2(c, d));
}

// ---------------- CSR build ----------------
__global__ void k_zero_counts() {
    int i = blockIdx.x * blockDim.x + threadIdx.x;
    if (i < NREL * NN) {
        ((int*)g_outcnt)[i] = 0;
        ((int*)g_incnt)[i]  = 0;
    }
}

__global__ void k_count(const int* __restrict__ edges) {
    extern __shared__ int smcnt[];            // [2*NN]
    const int r = blockIdx.y, b = blockIdx.x;
    int* so = smcnt;
    int* si = smcnt + NN;
    for (int i = threadIdx.x; i < 2 * NN; i += blockDim.x) smcnt[i] = 0;
    __syncthreads();
    const int per = NE / CB;
    const int e0 = b * per;
    const int* es = edges + (size_t)r * 2 * NE;
    for (int e = e0 + threadIdx.x * 4; e < e0 + per; e += blockDim.x * 4) {
        int4 s = *reinterpret_cast<const int4*>(es + e);
        int4 d = *reinterpret_cast<const int4*>(es + NE + e);
        atomicAdd(&so[s.x], 1); atomicAdd(&so[s.y], 1);
        atomicAdd(&so[s.z], 1); atomicAdd(&so[s.w], 1);
        atomicAdd(&si[d.x], 1); atomicAdd(&si[d.y], 1);
        atomicAdd(&si[d.z], 1); atomicAdd(&si[d.w], 1);
    }
    __syncthreads();
    for (int i = threadIdx.x; i < NN; i += blockDim.x) {
        int v = so[i];
        if (v) atomicAdd(&g_outcnt[r][i], v);
        v = si[i];
        if (v) atomicAdd(&g_incnt[r][i], v);
    }
}

__global__ void k_scan() {
    int r = blockIdx.x;
    int tid = threadIdx.x;          // 1024 threads
    int base = tid * 8;
    int c[8];
    int s = 0;
#pragma unroll
    for (int i = 0; i < 8; i++) { c[i] = g_incnt[r][base + i]; s += c[i]; }

    int lane = tid & 31, w = tid >> 5;
    int incl = s;
#pragma unroll
    for (int o = 1; o < 32; o <<= 1) {
        int v = __shfl_up_sync(0xffffffffu, incl, o);
        if (lane >= o) incl += v;
    }
    __shared__ int wsum[32];
    if (lane == 31) wsum[w] = incl;
    __syncthreads();
    if (w == 0) {
        int v = wsum[lane];
#pragma unroll
        for (int o = 1; o < 32; o <<= 1) {
            int t = __shfl_up_sync(0xffffffffu, v, o);
            if (lane >= o) v += t;
        }
        wsum[lane] = v;
    }
    __syncthreads();
    int excl = (incl - s) + (w > 0 ? wsum[w - 1] : 0);
    int run = excl;
#pragma unroll
    for (int i = 0; i < 8; i++) {
        g_rowptr[r][base + i] = run;
        g_fill[r][base + i]   = run;
        run += c[i];
        int ic = c[i] > 0 ? c[i] : 1;
        g_ininv[r][base + i] = rsqrtf((float)ic);
        int oc = g_outcnt[r][base + i];
        if (oc < 1) oc = 1;
        g_outinv[r][base + i] = rsqrtf((float)oc);
    }
    if (tid == 1023) g_rowptr[r][NN] = run;
}

__global__ void k_fill(const int* __restrict__ edges) {
    int i = (blockIdx.x * blockDim.x + threadIdx.x) * 4;
    if (i >= NREL * NE) return;
    int r = i / NE, e = i - r * NE;
    int4 src = *reinterpret_cast<const int4*>(edges + (size_t)r * 2 * NE + e);
    int4 dst = *reinterpret_cast<const int4*>(edges + (size_t)r * 2 * NE + NE + e);
    g_srcs[r][atomicAdd(&g_fill[r][dst.x], 1)] = src.x;
    g_srcs[r][atomicAdd(&g_fill[r][dst.y], 1)] = src.y;
    g_srcs[r][atomicAdd(&g_fill[r][dst.z], 1)] = src.z;
    g_srcs[r][atomicAdd(&g_fill[r][dst.w], 1)] = src.w;
}

// ---------------- conv GEMM batched over relations --------------------------
template <typename T>
__global__ void k_conv_b(const float* __restrict__ A0, const float* __restrict__ A1,
                         const float* __restrict__ A2, const float* __restrict__ Wb,
                         const float* __restrict__ scaleb, int K, int Nh,
                         T* __restrict__ xsbase, size_t xstride, uint32_t rpat) {
    const int r = (rpat >> (4 * blockIdx.z)) & 0xF;
    const int smap[6] = {0, 1, 0, 2, 2, 1};
    const float* A;
    if (A1 == nullptr) {
        A = A0 + (size_t)r * NN * K;
    } else {
        int si = smap[r];
        A = (si == 0) ? A0 : (si == 1) ? A1 : A2;
    }
    const float* W = Wb + (size_t)r * K * Nh;
    T* Xs = xsbase + (size_t)r * xstride;
    const float* scale = scaleb + r * NN;

    __shared__ float As[16][64];
    __shared__ float Bs[16][64];
    int tid = threadIdx.x;
    int bx = blockIdx.x, by = blockIdx.y;
    int aRow = tid >> 2, aCol = (tid & 3) * 4;
    int bRow = tid >> 4, bCol = (tid & 15) * 4;
    int tx = tid & 15, ty = tid >> 4;
    float acc[4][4] = {};
    const float* Ap = A + (size_t)(by * 64) * K;
    float scl = scale[by * 64 + aRow];

    for (int k0 = 0; k0 < K; k0 += 16) {
        float4 av = *(const float4*)(Ap + (size_t)aRow * K + k0 + aCol);
        As[aCol + 0][aRow] = av.x * scl;
        As[aCol + 1][aRow] = av.y * scl;
        As[aCol + 2][aRow] = av.z * scl;
        As[aCol + 3][aRow] = av.w * scl;
        float4 bv = *(const float4*)(W + (size_t)(k0 + bRow) * Nh + bx * 64 + bCol);
        *(float4*)&Bs[bRow][bCol] = bv;
        __syncthreads();
#pragma unroll
        for (int kk = 0; kk < 16; kk++) {
            float a[4], b[4];
#pragma unroll
            for (int i = 0; i < 4; i++) a[i] = As[kk][ty * 4 + i];
#pragma unroll
            for (int j = 0; j < 4; j++) b[j] = Bs[kk][tx * 4 + j];
#pragma unroll
            for (int i = 0; i < 4; i++)
#pragma unroll
                for (int j = 0; j < 4; j++) acc[i][j] += a[i] * b[j];
        }
        __syncthreads();
    }
    int row0 = by * 64 + ty * 4, col0 = bx * 64 + tx * 4;
#pragma unroll
    for (int i = 0; i < 4; i++)
        store4(Xs + (size_t)(row0 + i) * Nh + col0,
               acc[i][0], acc[i][1], acc[i][2], acc[i][3]);
}

// ---------------- aggregation helpers ----------------
__device__ __forceinline__ float4 f4add(float4 a, float4 b) {
    a.x += b.x; a.y += b.y; a.z += b.z; a.w += b.w; return a;
}
__device__ __forceinline__ float4 f4fma(float4 a, float s, float4 acc) {
    acc.x += a.x * s; acc.y += a.y * s; acc.z += a.z * s; acc.w += a.w * s; return acc;
}

// post-GEMM agg: both relations interleaved
__global__ void k_agg_v(const float* __restrict__ bias, int tbase) {
    const int t = tbase + blockIdx.y;
    const int n = blockIdx.x * blockDim.y + threadIdx.y;
    const int lane = threadIdx.x;     // 0..15
    const int RA[3] = {1, 0, 2};
    const int RB[3] = {3, 4, 5};
    const int r0 = RA[t], r1 = RB[t];
    const __half* xa = g_xsh[r0];
    const __half* xb = g_xsh[r1];
    const int* sa_ = g_srcs[r0];
    const int* sb_ = g_srcs[r1];
    int ea = g_rowptr[r0][n], ea1 = g_rowptr[r0][n + 1];
    int eb = g_rowptr[r1][n], eb1 = g_rowptr[r1][n + 1];
    float4 sA = make_float4(0.f, 0.f, 0.f, 0.f);
    float4 sB = make_float4(0.f, 0.f, 0.f, 0.f);

    while (ea + 7 < ea1 && eb + 7 < eb1) {
        uint2 a0 = reinterpret_cast<const uint2*>(xa + (size_t)sa_[ea] * 64)[lane];
        uint2 a1 = reinterpret_cast<const uint2*>(xa + (size_t)sa_[ea + 1] * 64)[lane];
        uint2 a2 = reinterpret_cast<const uint2*>(xa + (size_t)sa_[ea + 2] * 64)[lane];
        uint2 a3 = reinterpret_cast<const uint2*>(xa + (size_t)sa_[ea + 3] * 64)[lane];
        uint2 a4 = reinterpret_cast<const uint2*>(xa + (size_t)sa_[ea + 4] * 64)[lane];
        uint2 a5 = reinterpret_cast<const uint2*>(xa + (size_t)sa_[ea + 5] * 64)[lane];
        uint2 a6 = reinterpret_cast<const uint2*>(xa + (size_t)sa_[ea + 6] * 64)[lane];
        uint2 a7 = reinterpret_cast<const uint2*>(xa + (size_t)sa_[ea + 7] * 64)[lane];
        uint2 b0 = reinterpret_cast<const uint2*>(xb + (size_t)sb_[eb] * 64)[lane];
        uint2 b1 = reinterpret_cast<const uint2*>(xb + (size_t)sb_[eb + 1] * 64)[lane];
        uint2 b2 = reinterpret_cast<const uint2*>(xb + (size_t)sb_[eb + 2] * 64)[lane];
        uint2 b3 = reinterpret_cast<const uint2*>(xb + (size_t)sb_[eb + 3] * 64)[lane];
        uint2 b4 = reinterpret_cast<const uint2*>(xb + (size_t)sb_[eb + 4] * 64)[lane];
        uint2 b5 = reinterpret_cast<const uint2*>(xb + (size_t)sb_[eb + 5] * 64)[lane];
        uint2 b6 = reinterpret_cast<const uint2*>(xb + (size_t)sb_[eb + 6] * 64)[lane];
        uint2 b7 = reinterpret_cast<const uint2*>(xb + (size_t)sb_[eb + 7] * 64)[lane];
        float4 pa0 = h4tof4(h2add(a0, a1));
        float4 pa1 = h4tof4(h2add(a2, a3));
        float4 pa2 = h4tof4(h2add(a4, a5));
        float4 pa3 = h4tof4(h2add(a6, a7));
        float4 pb0 = h4tof4(h2add(b0, b1));
        float4 pb1 = h4tof4(h2add(b2, b3));
        float4 pb2 = h4tof4(h2add(b4, b5));
        float4 pb3 = h4tof4(h2add(b6, b7));
        sA = f4add(sA, f4add(f4add(pa0, pa1), f4add(pa2, pa3)));
        sB = f4add(sB, f4add(f4add(pb0, pb1), f4add(pb2, pb3)));
        ea += 8; eb += 8;
    }
    for (; ea + 7 < ea1; ea += 8) {
        uint2 a0 = reinterpret_cast<const uint2*>(xa + (size_t)sa_[ea] * 64)[lane];
        uint2 a1 = reinterpret_cast<const uint2*>(xa + (size_t)sa_[ea + 1] * 64)[lane];
        uint2 a2 = reinterpret_cast<const uint2*>(xa + (size_t)sa_[ea + 2] * 64)[lane];
        uint2 a3 = reinterpret_cast<const uint2*>(xa + (size_t)sa_[ea + 3] * 64)[lane];
        uint2 a4 = reinterpret_cast<const uint2*>(xa + (size_t)sa_[ea + 4] * 64)[lane];
        uint2 a5 = reinterpret_cast<const uint2*>(xa + (size_t)sa_[ea + 5] * 64)[lane];
        uint2 a6 = reinterpret_cast<const uint2*>(xa + (size_t)sa_[ea + 6] * 64)[lane];
        uint2 a7 = reinterpret_cast<const uint2*>(xa + (size_t)sa_[ea + 7] * 64)[lane];
        float4 p0 = h4tof4(h2add(a0, a1));
        float4 p1 = h4tof4(h2add(a2, a3));
        float4 p2 = h4tof4(h2add(a4, a5));
        float4 p3 = h4tof4(h2add(a6, a7));
        sA = f4add(sA, f4add(f4add(p0, p1), f4add(p2, p3)));
    }
    for (; ea < ea1; ea++)
        sA = f4add(sA, h4tof4(reinterpret_cast<const uint2*>(xa + (size_t)sa_[ea] * 64)[lane]));
    for (; eb + 7 < eb1; eb += 8) {
        uint2 b0 = reinterpret_cast<const uint2*>(xb + (size_t)sb_[eb] * 64)[lane];
        uint2 b1 = reinterpret_cast<const uint2*>(xb + (size_t)sb_[eb + 1] * 64)[lane];
        uint2 b2 = reinterpret_cast<const uint2*>(xb + (size_t)sb_[eb + 2] * 64)[lane];
        uint2 b3 = reinterpret_cast<const uint2*>(xb + (size_t)sb_[eb + 3] * 64)[lane];
        uint2 b4 = reinterpret_cast<const uint2*>(xb + (size_t)sb_[eb + 4] * 64)[lane];
        uint2 b5 = reinterpret_cast<const uint2*>(xb + (size_t)sb_[eb + 5] * 64)[lane];
        uint2 b6 = reinterpret_cast<const uint2*>(xb + (size_t)sb_[eb + 6] * 64)[lane];
        uint2 b7 = reinterpret_cast<const uint2*>(xb + (size_t)sb_[eb + 7] * 64)[lane];
        float4 p0 = h4tof4(h2add(b0, b1));
        float4 p1 = h4tof4(h2add(b2, b3));
        float4 p2 = h4tof4(h2add(b4, b5));
        float4 p3 = h4tof4(h2add(b6, b7));
        sB = f4add(sB, f4add(f4add(p0, p1), f4add(p2, p3)));
    }
    for (; eb < eb1; eb++)
        sB = f4add(sB, h4tof4(reinterpret_cast<const uint2*>(xb + (size_t)sb_[eb] * 64)[lane]));

    float4 acc = f4add(reinterpret_cast<const float4*>(bias + r0 * 64)[lane],
                       reinterpret_cast<const float4*>(bias + r1 * 64)[lane]);
    acc = f4fma(sA, g_ininv[r0][n], acc);
    acc = f4fma(sB, g_ininv[r1][n], acc);
    reinterpret_cast<float4*>(g_node[t] + (size_t)n * 64)[lane] = acc;
    reinterpret_cast<uint2*>(g_nodeh[t] + (size_t)n * 64)[lane] =
        make_uint2(pack_h2(acc.x, acc.y), pack_h2(acc.z, acc.w));
}

// pre-GEMM agg (layer 3): relations {1,3}, dst rows [0,4096) only
__global__ void k_aggpre() {
    const int r = 1 + 2 * blockIdx.y;           // 1, 3
    const int n = blockIdx.x * blockDim.y + threadIdx.y;   // < 4096
    const int lane = threadIdx.x;     // 0..15
    const int smap[6] = {0, 1, 0, 2, 2, 1};
    const __half* x = g_nodeh[smap[r]];
    const float* oi = g_outinv[r];
    const int* srcs = g_srcs[r];
    int e0 = g_rowptr[r][n], e1 = g_rowptr[r][n + 1];
    float4 acc = make_float4(0.f, 0.f, 0.f, 0.f);
    int e = e0;
    for (; e + 7 < e1; e += 8) {
        int s0 = srcs[e], s1 = srcs[e + 1], s2 = srcs[e + 2], s3 = srcs[e + 3];
        int s4 = srcs[e + 4], s5 = srcs[e + 5], s6 = srcs[e + 6], s7 = srcs[e + 7];
        uint2 u0 = reinterpret_cast<const uint2*>(x + (size_t)s0 * 64)[lane];
        uint2 u1 = reinterpret_cast<const uint2*>(x + (size_t)s1 * 64)[lane];
        uint2 u2 = reinterpret_cast<const uint2*>(x + (size_t)s2 * 64)[lane];
        uint2 u3 = reinterpret_cast<const uint2*>(x + (size_t)s3 * 64)[lane];
        uint2 u4 = reinterpret_cast<const uint2*>(x + (size_t)s4 * 64)[lane];
        uint2 u5 = reinterpret_cast<const uint2*>(x + (size_t)s5 * 64)[lane];
        uint2 u6 = reinterpret_cast<const uint2*>(x + (size_t)s6 * 64)[lane];
        uint2 u7 = reinterpret_cast<const uint2*>(x + (size_t)s7 * 64)[lane];
        acc = f4fma(h4tof4(u0), oi[s0], acc);
        acc = f4fma(h4tof4(u1), oi[s1], acc);
        acc = f4fma(h4tof4(u2), oi[s2], acc);
        acc = f4fma(h4tof4(u3), oi[s3], acc);
        acc = f4fma(h4tof4(u4), oi[s4], acc);
        acc = f4fma(h4tof4(u5), oi[s5], acc);
        acc = f4fma(h4tof4(u6), oi[s6], acc);
        acc = f4fma(h4tof4(u7), oi[s7], acc);
    }
    for (; e < e1; e++) {
        int s0 = srcs[e];
        uint2 u0 = reinterpret_cast<const uint2*>(x + (size_t)s0 * 64)[lane];
        acc = f4fma(h4tof4(u0), oi[s0], acc);
    }
    reinterpret_cast<float4*>(g_agg[r] + (size_t)n * 64)[lane] = acc;
}

// ---------------- fused combine + L1-normalize (rows [0,4096)) -------------
__global__ void k_l1norm(const float* __restrict__ b3,
                         float* __restrict__ out, __half* __restrict__ feh) {
    int row = blockIdx.x;
    int h = threadIdx.x;  // 128
    float v = g_xs32[1][(size_t)row * OUTD + h] + g_xs32[3][(size_t)row * OUTD + h]
            + b3[128 + h] + b3[384 + h];
    float a = fabsf(v);
#pragma unroll
    for (int o = 16; o > 0; o >>= 1) a += __shfl_xor_sync(0xffffffffu, a, o);
    __shared__ float sh[4];
    if ((h & 31) == 0) sh[h >> 5] = a;
    __syncthreads();
    float tot = sh[0] + sh[1] + sh[2] + sh[3];
    float r = v / fmaxf(tot, 1e-12f);
    out[(size_t)row * OUTD + h] = r;
    feh[(size_t)row * OUTD + h] = __float2half_rn(r);
}

// ---------------- Adj fp32 -> fp16 -----------------------------------------
__global__ void k_cvt(const float4* __restrict__ src, __half* __restrict__ dst) {
    size_t i = (size_t)blockIdx.x * blockDim.x + threadIdx.x;
    float4 v = src[i];
    uint2 p = make_uint2(pack_h2(v.x, v.y), pack_h2(v.z, v.w));
    *reinterpret_cast<uint2*>(dst + 4 * i) = p;
}

// ---------------- weight transpose fp16: B[K][N] -> Bt[N][K] ---------------
__global__ void k_tsp(const float* __restrict__ B, __half* __restrict__ th,
                      int K, int N) {
    __shared__ float s[32][33];
    int n0 = blockIdx.x * 32, k0 = blockIdx.y * 32;
    int tx = threadIdx.x, ty = threadIdx.y;
#pragma unroll
    for (int i = 0; i < 32; i += 8)
        s[ty + i][tx] = B[(size_t)(k0 + ty + i) * N + n0 + tx];
    __syncthreads();
#pragma unroll
    for (int i = 0; i < 32; i += 8) {
        int n = n0 + ty + i, k = k0 + tx;
        th[(size_t)n * K + k] = __float2half_rn(s[tx][ty + i]);
    }
}

// ---------------- mma.sync + ldmatrix + cp.async plumbing ------------------
__device__ __forceinline__ uint32_t s2u(const void* p) {
    uint32_t a;
    asm("{ .reg .u64 t; cvta.to.shared.u64 t, %1; cvt.u32.u64 %0, t; }" : "=r"(a) : "l"(p));
    return a;
}
__device__ __forceinline__ void mma_f16(float* d, const uint32_t* a, const uint32_t* b) {
    asm volatile(
        "mma.sync.aligned.m16n8k16.row.col.f32.f16.f16.f32 "
        "{%0,%1,%2,%3}, {%4,%5,%6,%7}, {%8,%9}, {%0,%1,%2,%3};"
        : "+f"(d[0]), "+f"(d[1]), "+f"(d[2]), "+f"(d[3])
        : "r"(a[0]), "r"(a[1]), "r"(a[2]), "r"(a[3]), "r"(b[0]), "r"(b[1]));
}
__device__ __forceinline__ void ldsm4(uint32_t* r, uint32_t addr) {
    asm volatile("ldmatrix.sync.aligned.m8n8.x4.shared.b16 {%0,%1,%2,%3}, [%4];"
                 : "=r"(r[0]), "=r"(r[1]), "=r"(r[2]), "=r"(r[3]) : "r"(addr));
}
__device__ __forceinline__ void cpa16(uint32_t s, const void* g) {
    asm volatile("cp.async.cg.shared.global [%0], [%1], 16;" :: "r"(s), "l"(g));
}
#define CP_COMMIT() asm volatile("cp.async.commit_group;" ::: "memory")
#define CP_WAIT2()  asm volatile("cp.async.wait_group 2;" ::: "memory")

// ---------------- MLP GEMM: fp16 single-pass, templated BN -----------------
template <int ACT, int OUT, bool HC, int NT>
__global__ void __launch_bounds__(256, 1)
k_tc(const __half* __restrict__ A_, const __half* __restrict__ Bh_,
     const float* __restrict__ bias, const float* __restrict__ Cin,
     float* __restrict__ Cf, __half* __restrict__ Oh, int N, int K) {
    constexpr int BN = NT * 16;
    constexpr uint32_t ASZ = 16384u;
    constexpr uint32_t STG = ASZ + (uint32_t)BN * 128u;
    extern __shared__ char smc[];
    const uint32_t sb = s2u(smc);
    const int tid = threadIdx.x, lane = tid & 31, warp = tid >> 5;
    const int wm = warp & 3, wn = warp >> 2;
    const int g = lane >> 2, tig = lane & 3;
    const int bm = blockIdx.y * 128, bn = blockIdx.x * BN;

    float c[2][NT][4];
#pragma unroll
    for (int i = 0; i < 2; i++)
#pragma unroll
        for (int j = 0; j < NT; j++)
#pragma unroll
            for (int q = 0; q < 4; q++) c[i][j][q] = 0.f;

    auto load_stage = [&](int s) {
        const uint32_t st = sb + (uint32_t)(s % 3) * STG;
        const int k0 = s * 64;
#pragma unroll
        for (int j = 0; j < (128 + BN) / 32; j++) {
            int cidx = tid + 256 * j;
            int row = cidx >> 3, kc = cidx & 7;
            if (row < 128) {
                uint32_t off = (uint32_t)(row * 128 + kc * 16);
                off ^= (off >> 3) & 0x70;
                cpa16(st + off, A_ + (size_t)(bm + row) * K + k0 + kc * 8);
            } else {
                int br = row - 128;
                uint32_t off = (uint32_t)(br * 128 + kc * 16);
                off ^= (off >> 3) & 0x70;
                cpa16(st + ASZ + off, Bh_ + (size_t)(bn + br) * K + k0 + kc * 8);
            }
        }
    };

    const int nst = K >> 6;
#pragma unroll
    for (int i = 0; i < 3; i++) {
        if (i < nst) load_stage(i);
        CP_COMMIT();
    }

    for (int s = 0; s < nst; s++) {
        CP_WAIT2();
        __syncthreads();
        const uint32_t st = sb + (uint32_t)(s % 3) * STG;
#pragma unroll
        for (int kk = 0; kk < 64; kk += 16) {
            uint32_t ah[2][4], bh[NT][2];
#pragma unroll
            for (int mt = 0; mt < 2; mt++) {
                int row = wm * 32 + mt * 16 + (lane & 15);
                uint32_t off = (uint32_t)(row * 128) + (uint32_t)(kk * 2) + (uint32_t)(lane & 16);
                off ^= (off >> 3) & 0x70;
                ldsm4(ah[mt], st + off);
            }
#pragma unroll
            for (int bt = 0; bt < NT / 2; bt++) {
                int row = wn * (8 * NT) + bt * 16 + ((lane >> 4) << 3) + (lane & 7);
                uint32_t off = (uint32_t)(row * 128) + (uint32_t)(kk * 2) + (uint32_t)((lane & 8) << 1);
                off ^= (off >> 3) & 0x70;
                uint32_t r[4];
                ldsm4(r, st + ASZ + off);
                bh[2 * bt][0] = r[0]; bh[2 * bt][1] = r[1];
                bh[2 * bt + 1][0] = r[2]; bh[2 * bt + 1][1] = r[3];
            }
#pragma unroll
            for (int mt = 0; mt < 2; mt++)
#pragma unroll
                for (int nt = 0; nt < NT; nt++)
                    mma_f16(c[mt][nt], ah[mt], bh[nt]);
        }
        __syncthreads();
        if (s + 3 < nst) load_stage(s + 3);
        CP_COMMIT();
    }

    // epilogue
#pragma unroll
    for (int mt = 0; mt < 2; mt++) {
#pragma unroll
        for (int nt = 0; nt < NT; nt++) {
            int m0 = bm + wm * 32 + mt * 16 + g;
            int n0 = bn + wn * (8 * NT) + nt * 8 + 2 * tig;
            float2 v0 = make_float2(c[mt][nt][0], c[mt][nt][1]);
            float2 v1 = make_float2(c[mt][nt][2], c[mt][nt][3]);
            if (HC) {
                float2 ci0 = *reinterpret_cast<const float2*>(Cin + (size_t)m0 * N + n0);
                float2 ci1 = *reinterpret_cast<const float2*>(Cin + (size_t)(m0 + 8) * N + n0);
                v0.x += ci0.x; v0.y += ci0.y; v1.x += ci1.x; v1.y += ci1.y;
            }
            if (bias) {
                float bx = bias[n0], by = bias[n0 + 1];
                v0.x += bx; v0.y += by; v1.x += bx; v1.y += by;
            }
            if (ACT == 1) {
                v0.x = fmaxf(v0.x, 0.f); v0.y = fmaxf(v0.y, 0.f);
                v1.x = fmaxf(v1.x, 0.f); v1.y = fmaxf(v1.y, 0.f);
            } else if (ACT == 2) {
                v0.x = 1.f / (1.f + __expf(-v0.x)); v0.y = 1.f / (1.f + __expf(-v0.y));
                v1.x = 1.f / (1.f + __expf(-v1.x)); v1.y = 1.f / (1.f + __expf(-v1.y));
            }
            if (OUT == 0) {
                *reinterpret_cast<float2*>(Cf + (size_t)m0 * N + n0) = v0;
                *reinterpret_cast<float2*>(Cf + (size_t)(m0 + 8) * N + n0) = v1;
            } else {
                *reinterpret_cast<uint32_t*>(Oh + (size_t)m0 * N + n0) = pack_h2(v0.x, v0.y);
                *reinterpret_cast<uint32_t*>(Oh + (size_t)(m0 + 8) * N + n0) = pack_h2(v1.x, v1.y);
            }
        }
    }
}

#define SM8  (3 * (16384 + 128 * 128))   // 96 KB  (NT=8)
#define SM16 (3 * (16384 + 256 * 128))   // 144 KB (NT=16)

// ---------------- orchestration ----------------
extern "C" void kernel_launch(void* const* d_in, const int* in_sizes, int n_in,
                              void* d_out, int out_size) {
    const float* hM  = (const float*)d_in[0];
    const float* hD  = (const float*)d_in[1];
    const float* hT  = (const float*)d_in[2];
    const float* W1  = (const float*)d_in[3];
    const float* b1  = (const float*)d_in[4];
    const float* W2  = (const float*)d_in[5];
    const float* b2  = (const float*)d_in[6];
    const float* W3  = (const float*)d_in[7];
    const float* b3  = (const float*)d_in[8];
    const float* Adj = (const float*)d_in[9];
    const float* f1w = (const float*)d_in[10];
    const float* f1b = (const float*)d_in[11];
    const float* f2w = (const float*)d_in[12];
    const float* f2b = (const float*)d_in[13];
    const float* f3w = (const float*)d_in[14];
    const float* f3b = (const float*)d_in[15];
    const float* f4w = (const float*)d_in[16];
    const float* f4b = (const float*)d_in[17];
    const int* edges = (const int*)d_in[18];

    float *p_node, *p_agg, *p_outinv, *p_ininv, *p_xs32, *p_x1f;
    __half *p_bth, *p_adjh, *p_feh, *p_x1h, *p_x2h, *p_x3h, *p_xsh;
    cudaGetSymbolAddress((void**)&p_node, g_node);
    cudaGetSymbolAddress((void**)&p_agg, g_agg);
    cudaGetSymbolAddress((void**)&p_outinv, g_outinv);
    cudaGetSymbolAddress((void**)&p_ininv, g_ininv);
    cudaGetSymbolAddress((void**)&p_xs32, g_xs32);
    cudaGetSymbolAddress((void**)&p_xsh, g_xsh);
    cudaGetSymbolAddress((void**)&p_bth, g_bth);
    cudaGetSymbolAddress((void**)&p_adjh, g_adjh);
    cudaGetSymbolAddress((void**)&p_feh, g_feh);
    cudaGetSymbolAddress((void**)&p_x1f, g_x1f);
    cudaGetSymbolAddress((void**)&p_x1h, g_x1h);
    cudaGetSymbolAddress((void**)&p_x2h, g_x2h);
    cudaGetSymbolAddress((void**)&p_x3h, g_x3h);

    float* fe   = (float*)d_out;                       // 4096 x 128
    float* outx = (float*)d_out + (size_t)MROW * OUTD; // 4096 x 8192

    static cudaStream_t s2 = nullptr, s3 = nullptr;
    static cudaEvent_t evFork = nullptr, evJoin = nullptr, evScan = nullptr, evFill = nullptr;
    if (s2 == nullptr) {
        cudaStreamCreateWithFlags(&s2, cudaStreamNonBlocking);
        cudaStreamCreateWithFlags(&s3, cudaStreamNonBlocking);
        cudaEventCreateWithFlags(&evFork, cudaEventDisableTiming);
        cudaEventCreateWithFlags(&evJoin, cudaEventDisableTiming);
        cudaEventCreateWithFlags(&evScan, cudaEventDisableTiming);
        cudaEventCreateWithFlags(&evFill, cudaEventDisableTiming);
        cudaFuncSetAttribute(k_tc<0, 0, false, 8>, cudaFuncAttributeMaxDynamicSharedMemorySize, SM8);
        cudaFuncSetAttribute(k_tc<1, 1, true, 8>,  cudaFuncAttributeMaxDynamicSharedMemorySize, SM8);
        cudaFuncSetAttribute(k_tc<1, 1, false, 8>, cudaFuncAttributeMaxDynamicSharedMemorySize, SM8);
        cudaFuncSetAttribute(k_tc<2, 0, false, 16>, cudaFuncAttributeMaxDynamicSharedMemorySize, SM16);
        cudaFuncSetAttribute(k_count, cudaFuncAttributeMaxDynamicSharedMemorySize, 2 * NN * 4);
    }

    // ---- fork s2: MLP prep + Adj GEMM (independent of GNN) ----
    cudaEventRecord(evFork, 0);
    cudaStreamWaitEvent(s2, evFork, 0);
    k_cvt<<<(MROW * ITEM / 4) / 256, 256, 0, s2>>>((const float4*)Adj, p_adjh);
    k_tsp<<<dim3(256 / 32, 8192 / 32), dim3(32, 8), 0, s2>>>(f1w, p_bth + O1A, 8192, 256);
    k_tsp<<<dim3(256 / 32, 128 / 32),  dim3(32, 8), 0, s2>>>(f1w + (size_t)ITEM * 256, p_bth + O1B, 128, 256);
    k_tsp<<<dim3(512 / 32, 256 / 32),  dim3(32, 8), 0, s2>>>(f2w, p_bth + O2, 256, 512);
    k_tsp<<<dim3(1024 / 32, 512 / 32), dim3(32, 8), 0, s2>>>(f3w, p_bth + O3, 512, 1024);
    k_tsp<<<dim3(8192 / 32, 1024 / 32), dim3(32, 8), 0, s2>>>(f4w, p_bth + O4, 1024, 8192);
    k_tc<0, 0, false, 8><<<dim3(2, 32), 256, SM8, s2>>>(
        p_adjh, p_bth + O1A, nullptr, nullptr, p_x1f, nullptr, 256, 8192);
    cudaEventRecord(evJoin, s2);

    // ---- main stream: CSR counts + scan ----
    k_zero_counts<<<(NREL * NN + 255) / 256, 256>>>();
    k_count<<<dim3(CB, NREL), 512, 2 * NN * 4>>>(edges);
    k_scan<<<NREL, 1024>>>();
    cudaEventRecord(evScan, 0);

    // ---- fork s3: CSR fill ----
    cudaStreamWaitEvent(s3, evScan, 0);
    k_fill<<<(NREL * NE / 4 + 255) / 256, 256, 0, s3>>>(edges);
    cudaEventRecord(evFill, s3);

    // ---- main: layer-1 conv overlaps fill ----
    k_conv_b<__half><<<dim3(1, NN / 64, 6), 256>>>(hM, hD, hT, W1, p_outinv, 256, 64,
                                                   p_xsh, (size_t)NN * 64, 0x543210u);
    cudaStreamWaitEvent(0, evFill, 0);
    k_agg_v<<<dim3(NN / 16, 3), dim3(16, 16)>>>(b1, 0);

    // layer 2: relations {0,2,4,5}, targets {D,T}
    k_conv_b<__half><<<dim3(1, NN / 64, 4), 256>>>(p_node, p_node + (size_t)NN * 128,
                                                   p_node + (size_t)2 * NN * 128, W2,
                                                   p_outinv, 64, 64, p_xsh, (size_t)NN * 64,
                                                   0x5420u);
    k_agg_v<<<dim3(NN / 16, 2), dim3(16, 16)>>>(b2, 1);

    // layer 3: relations {1,3}, dst rows [0,4096) only
    k_aggpre<<<dim3(MROW / 16, 2), dim3(16, 16)>>>();
    k_conv_b<float><<<dim3(2, MROW / 64, 2), 256>>>(p_agg, nullptr, nullptr, W3, p_ininv,
                                                    64, 128, p_xs32, (size_t)NN * 128, 0x31u);
    k_l1norm<<<MROW, 128>>>(b3, fe, p_feh);

    // ---- join + MLP tail (serial full-M: R14 M-split regressed) ----
    cudaStreamWaitEvent(0, evJoin, 0);

    k_tc<1, 1, true, 8><<<dim3(2, 32), 256, SM8>>>(
        p_feh, p_bth + O1B, f1b, p_x1f, nullptr, p_x1h, 256, 128);
    k_tc<1, 1, false, 8><<<dim3(4, 32), 256, SM8>>>(
        p_x1h, p_bth + O2, f2b, nullptr, nullptr, p_x2h, 512, 256);
    k_tc<1, 1, false, 8><<<dim3(8, 32), 256, SM8>>>(
        p_x2h, p_bth + O3, f3b, nullptr, nullptr, p_x3h, 1024, 512);
    k_tc<2, 0, false, 16><<<dim3(32, 32), 256, SM16>>>(
        p_x3h, p_bth + O4, f4b, nullptr, outx, nullptr, 8192, 1024);
}

// round 16
// speedup vs baseline: 1.0783x; 1.0191x over previous
#include <cuda_runtime.h>
#include <cuda_fp16.h>
#include <stdint.h>
#include <math.h>

#define NN   8192
#define NE   500000
#define NREL 6
#define FEAT 256
#define HIDD 64
#define OUTD 128
#define MROW 4096   // SIZE
#define ITEM 8192
#define CB   20     // blocks per relation for count/fill (NE/CB=25000, %4==0)

// ---------------- scratch (device globals: allocation-free) ----------------
__device__ int   g_outcnt[NREL][NN];
__device__ int   g_incnt [NREL][NN];
__device__ float g_outinv[NREL][NN];
__device__ float g_ininv [NREL][NN];
__device__ int   g_rowptr[NREL][NN + 1];
__device__ int   g_fill  [NREL][NN];
__device__ int   g_srcs  [NREL][NE];
__device__ __half g_xsh [NREL][NN * 64];    // layers 1-2 conv outputs (gathered)
__device__ float g_xs32 [NREL][NN * 128];   // layer-3 conv outputs (fp32, rows<4096)
__device__ float g_agg  [NREL][NN * 64];    // layer-3 pre-aggregated inputs
__device__ float g_node [3][NN * 128];      // trunk state fp32
__device__ __half g_nodeh[3][NN * 64];      // fp16 shadow for layer-3 gather

// pre-transposed fp16 weights
#define O1A 0                            // f1w top^T [256][8192]
#define O1B 2097152                      // f1w bot^T [256][128]
#define O2  2129920                      // f2w^T     [512][256]
#define O3  2260992                      // f3w^T     [1024][512]
#define O4  2785280                      // f4w^T     [8192][1024]
#define BT_TOTAL 11173888
__device__ __half g_bth[BT_TOTAL];

// fp16 activations
__device__ __half g_adjh[(size_t)MROW * ITEM];
__device__ __half g_feh[MROW * OUTD];
__device__ float  g_x1f[MROW * 256];        // f1 Adj-partial (fp32)
__device__ __half g_x1h[MROW * 256];
__device__ __half g_x2h[MROW * 512];
__device__ __half g_x3h[MROW * 1024];

// ---------------- fp16 helpers ----------------
__device__ __forceinline__ uint32_t pack_h2(float x, float y) {
    __half2 h = __floats2half2_rn(x, y);
    return *reinterpret_cast<uint32_t*>(&h);
}
__device__ __forceinline__ float4 h4tof4(uint2 u) {
    float2 a = __half22float2(*reinterpret_cast<__half2*>(&u.x));
    float2 b = __half22float2(*reinterpret_cast<__half2*>(&u.y));
    return make_float4(a.x, a.y, b.x, b.y);
}
__device__ __forceinline__ uint2 h2add(uint2 a, uint2 b) {
    __half2* A = reinterpret_cast<__half2*>(&a);
    __half2* B = reinterpret_cast<__half2*>(&b);
    uint2 r;
    reinterpret_cast<__half2*>(&r)[0] = __hadd2(A[0], B[0]);
    reinterpret_cast<__half2*>(&r)[1] = __hadd2(A[1], B[1]);
    return r;
}
__device__ __forceinline__ void store4(float* p, float a, float b, float c, float d) {
    *reinterpret_cast<float4*>(p) = make_float4(a, b, c, d);
}
__device__ __forceinline__ void store4(__half* p, float a, float b, float c, float d) {
    *reinterpret_cast<uint2*>(p) = make_uint2(pack_h2(a, b), pack_h2(c, d));
}

// ---------------- CSR build ----------------
__global__ void k_zero_counts() {
    int i = blockIdx.x * blockDim.x + threadIdx.x;
    if (i < NREL * NN) {
        ((int*)g_outcnt)[i] = 0;
        ((int*)g_incnt)[i]  = 0;
    }
}

__global__ void k_count(const int* __restrict__ edges) {
    extern __shared__ int smcnt[];            // [2*NN]
    const int r = blockIdx.y, b = blockIdx.x;
    int* so = smcnt;
    int* si = smcnt + NN;
    for (int i = threadIdx.x; i < 2 * NN; i += blockDim.x) smcnt[i] = 0;
    __syncthreads();
    const int per = NE / CB;
    const int e0 = b * per;
    const int* es = edges + (size_t)r * 2 * NE;
    for (int e = e0 + threadIdx.x * 4; e < e0 + per; e += blockDim.x * 4) {
        int4 s = *reinterpret_cast<const int4*>(es + e);
        int4 d = *reinterpret_cast<const int4*>(es + NE + e);
        atomicAdd(&so[s.x], 1); atomicAdd(&so[s.y], 1);
        atomicAdd(&so[s.z], 1); atomicAdd(&so[s.w], 1);
        atomicAdd(&si[d.x], 1); atomicAdd(&si[d.y], 1);
        atomicAdd(&si[d.z], 1); atomicAdd(&si[d.w], 1);
    }
    __syncthreads();
    for (int i = threadIdx.x; i < NN; i += blockDim.x) {
        int v = so[i];
        if (v) atomicAdd(&g_outcnt[r][i], v);
        v = si[i];
        if (v) atomicAdd(&g_incnt[r][i], v);
    }
}

__global__ void k_scan() {
    int r = blockIdx.x;
    int tid = threadIdx.x;          // 1024 threads
    int base = tid * 8;
    int c[8];
    int s = 0;
#pragma unroll
    for (int i = 0; i < 8; i++) { c[i] = g_incnt[r][base + i]; s += c[i]; }

    int lane = tid & 31, w = tid >> 5;
    int incl = s;
#pragma unroll
    for (int o = 1; o < 32; o <<= 1) {
        int v = __shfl_up_sync(0xffffffffu, incl, o);
        if (lane >= o) incl += v;
    }
    __shared__ int wsum[32];
    if (lane == 31) wsum[w] = incl;
    __syncthreads();
    if (w == 0) {
        int v = wsum[lane];
#pragma unroll
        for (int o = 1; o < 32; o <<= 1) {
            int t = __shfl_up_sync(0xffffffffu, v, o);
            if (lane >= o) v += t;
        }
        wsum[lane] = v;
    }
    __syncthreads();
    int excl = (incl - s) + (w > 0 ? wsum[w - 1] : 0);
    int run = excl;
#pragma unroll
    for (int i = 0; i < 8; i++) {
        g_rowptr[r][base + i] = run;
        g_fill[r][base + i]   = run;
        run += c[i];
        int ic = c[i] > 0 ? c[i] : 1;
        g_ininv[r][base + i] = rsqrtf((float)ic);
        int oc = g_outcnt[r][base + i];
        if (oc < 1) oc = 1;
        g_outinv[r][base + i] = rsqrtf((float)oc);
    }
    if (tid == 1023) g_rowptr[r][NN] = run;
}

// two-phase privatized fill: smem histogram -> range reservation -> smem-cursor scatter
__global__ void k_fill(const int* __restrict__ edges) {
    __shared__ int scur[NN];                  // 32 KB
    const int r = blockIdx.y, b = blockIdx.x;
    for (int i = threadIdx.x; i < NN; i += blockDim.x) scur[i] = 0;
    __syncthreads();
    const int per = NE / CB;
    const int e0 = b * per;
    const int* es = edges + (size_t)r * 2 * NE;
    // phase 1: local histogram of dst
    for (int e = e0 + threadIdx.x * 4; e < e0 + per; e += blockDim.x * 4) {
        int4 d = *reinterpret_cast<const int4*>(es + NE + e);
        atomicAdd(&scur[d.x], 1); atomicAdd(&scur[d.y], 1);
        atomicAdd(&scur[d.z], 1); atomicAdd(&scur[d.w], 1);
    }
    __syncthreads();
    // phase 2: reserve global ranges; scur becomes the running cursor
    for (int i = threadIdx.x; i < NN; i += blockDim.x) {
        int c = scur[i];
        if (c) scur[i] = atomicAdd(&g_fill[r][i], c);
    }
    __syncthreads();
    // phase 3: scatter via smem cursors
    int* dstv = g_srcs[r];
    for (int e = e0 + threadIdx.x * 4; e < e0 + per; e += blockDim.x * 4) {
        int4 s = *reinterpret_cast<const int4*>(es + e);
        int4 d = *reinterpret_cast<const int4*>(es + NE + e);
        dstv[atomicAdd(&scur[d.x], 1)] = s.x;
        dstv[atomicAdd(&scur[d.y], 1)] = s.y;
        dstv[atomicAdd(&scur[d.z], 1)] = s.z;
        dstv[atomicAdd(&scur[d.w], 1)] = s.w;
    }
}

// ---------------- conv GEMM batched over relations --------------------------
template <typename T>
__global__ void k_conv_b(const float* __restrict__ A0, const float* __restrict__ A1,
                         const float* __restrict__ A2, const float* __restrict__ Wb,
                         const float* __restrict__ scaleb, int K, int Nh,
                         T* __restrict__ xsbase, size_t xstride, uint32_t rpat) {
    const int r = (rpat >> (4 * blockIdx.z)) & 0xF;
    const int smap[6] = {0, 1, 0, 2, 2, 1};
    const float* A;
    if (A1 == nullptr) {
        A = A0 + (size_t)r * NN * K;
    } else {
        int si = smap[r];
        A = (si == 0) ? A0 : (si == 1) ? A1 : A2;
    }
    const float* W = Wb + (size_t)r * K * Nh;
    T* Xs = xsbase + (size_t)r * xstride;
    const float* scale = scaleb + r * NN;

    __shared__ float As[16][64];
    __shared__ float Bs[16][64];
    int tid = threadIdx.x;
    int bx = blockIdx.x, by = blockIdx.y;
    int aRow = tid >> 2, aCol = (tid & 3) * 4;
    int bRow = tid >> 4, bCol = (tid & 15) * 4;
    int tx = tid & 15, ty = tid >> 4;
    float acc[4][4] = {};
    const float* Ap = A + (size_t)(by * 64) * K;
    float scl = scale[by * 64 + aRow];

    for (int k0 = 0; k0 < K; k0 += 16) {
        float4 av = *(const float4*)(Ap + (size_t)aRow * K + k0 + aCol);
        As[aCol + 0][aRow] = av.x * scl;
        As[aCol + 1][aRow] = av.y * scl;
        As[aCol + 2][aRow] = av.z * scl;
        As[aCol + 3][aRow] = av.w * scl;
        float4 bv = *(const float4*)(W + (size_t)(k0 + bRow) * Nh + bx * 64 + bCol);
        *(float4*)&Bs[bRow][bCol] = bv;
        __syncthreads();
#pragma unroll
        for (int kk = 0; kk < 16; kk++) {
            float a[4], b[4];
#pragma unroll
            for (int i = 0; i < 4; i++) a[i] = As[kk][ty * 4 + i];
#pragma unroll
            for (int j = 0; j < 4; j++) b[j] = Bs[kk][tx * 4 + j];
#pragma unroll
            for (int i = 0; i < 4; i++)
#pragma unroll
                for (int j = 0; j < 4; j++) acc[i][j] += a[i] * b[j];
        }
        __syncthreads();
    }
    int row0 = by * 64 + ty * 4, col0 = bx * 64 + tx * 4;
#pragma unroll
    for (int i = 0; i < 4; i++)
        store4(Xs + (size_t)(row0 + i) * Nh + col0,
               acc[i][0], acc[i][1], acc[i][2], acc[i][3]);
}

// ---------------- aggregation helpers ----------------
__device__ __forceinline__ float4 f4add(float4 a, float4 b) {
    a.x += b.x; a.y += b.y; a.z += b.z; a.w += b.w; return a;
}
__device__ __forceinline__ float4 f4fma(float4 a, float s, float4 acc) {
    acc.x += a.x * s; acc.y += a.y * s; acc.z += a.z * s; acc.w += a.w * s; return acc;
}

// post-GEMM agg: both relations interleaved
__global__ void k_agg_v(const float* __restrict__ bias, int tbase) {
    const int t = tbase + blockIdx.y;
    const int n = blockIdx.x * blockDim.y + threadIdx.y;
    const int lane = threadIdx.x;     // 0..15
    const int RA[3] = {1, 0, 2};
    const int RB[3] = {3, 4, 5};
    const int r0 = RA[t], r1 = RB[t];
    const __half* xa = g_xsh[r0];
    const __half* xb = g_xsh[r1];
    const int* sa_ = g_srcs[r0];
    const int* sb_ = g_srcs[r1];
    int ea = g_rowptr[r0][n], ea1 = g_rowptr[r0][n + 1];
    int eb = g_rowptr[r1][n], eb1 = g_rowptr[r1][n + 1];
    float4 sA = make_float4(0.f, 0.f, 0.f, 0.f);
    float4 sB = make_float4(0.f, 0.f, 0.f, 0.f);

    while (ea + 7 < ea1 && eb + 7 < eb1) {
        uint2 a0 = reinterpret_cast<const uint2*>(xa + (size_t)sa_[ea] * 64)[lane];
        uint2 a1 = reinterpret_cast<const uint2*>(xa + (size_t)sa_[ea + 1] * 64)[lane];
        uint2 a2 = reinterpret_cast<const uint2*>(xa + (size_t)sa_[ea + 2] * 64)[lane];
        uint2 a3 = reinterpret_cast<const uint2*>(xa + (size_t)sa_[ea + 3] * 64)[lane];
        uint2 a4 = reinterpret_cast<const uint2*>(xa + (size_t)sa_[ea + 4] * 64)[lane];
        uint2 a5 = reinterpret_cast<const uint2*>(xa + (size_t)sa_[ea + 5] * 64)[lane];
        uint2 a6 = reinterpret_cast<const uint2*>(xa + (size_t)sa_[ea + 6] * 64)[lane];
        uint2 a7 = reinterpret_cast<const uint2*>(xa + (size_t)sa_[ea + 7] * 64)[lane];
        uint2 b0 = reinterpret_cast<const uint2*>(xb + (size_t)sb_[eb] * 64)[lane];
        uint2 b1 = reinterpret_cast<const uint2*>(xb + (size_t)sb_[eb + 1] * 64)[lane];
        uint2 b2 = reinterpret_cast<const uint2*>(xb + (size_t)sb_[eb + 2] * 64)[lane];
        uint2 b3 = reinterpret_cast<const uint2*>(xb + (size_t)sb_[eb + 3] * 64)[lane];
        uint2 b4 = reinterpret_cast<const uint2*>(xb + (size_t)sb_[eb + 4] * 64)[lane];
        uint2 b5 = reinterpret_cast<const uint2*>(xb + (size_t)sb_[eb + 5] * 64)[lane];
        uint2 b6 = reinterpret_cast<const uint2*>(xb + (size_t)sb_[eb + 6] * 64)[lane];
        uint2 b7 = reinterpret_cast<const uint2*>(xb + (size_t)sb_[eb + 7] * 64)[lane];
        float4 pa0 = h4tof4(h2add(a0, a1));
        float4 pa1 = h4tof4(h2add(a2, a3));
        float4 pa2 = h4tof4(h2add(a4, a5));
        float4 pa3 = h4tof4(h2add(a6, a7));
        float4 pb0 = h4tof4(h2add(b0, b1));
        float4 pb1 = h4tof4(h2add(b2, b3));
        float4 pb2 = h4tof4(h2add(b4, b5));
        float4 pb3 = h4tof4(h2add(b6, b7));
        sA = f4add(sA, f4add(f4add(pa0, pa1), f4add(pa2, pa3)));
        sB = f4add(sB, f4add(f4add(pb0, pb1), f4add(pb2, pb3)));
        ea += 8; eb += 8;
    }
    for (; ea + 7 < ea1; ea += 8) {
        uint2 a0 = reinterpret_cast<const uint2*>(xa + (size_t)sa_[ea] * 64)[lane];
        uint2 a1 = reinterpret_cast<const uint2*>(xa + (size_t)sa_[ea + 1] * 64)[lane];
        uint2 a2 = reinterpret_cast<const uint2*>(xa + (size_t)sa_[ea + 2] * 64)[lane];
        uint2 a3 = reinterpret_cast<const uint2*>(xa + (size_t)sa_[ea + 3] * 64)[lane];
        uint2 a4 = reinterpret_cast<const uint2*>(xa + (size_t)sa_[ea + 4] * 64)[lane];
        uint2 a5 = reinterpret_cast<const uint2*>(xa + (size_t)sa_[ea + 5] * 64)[lane];
        uint2 a6 = reinterpret_cast<const uint2*>(xa + (size_t)sa_[ea + 6] * 64)[lane];
        uint2 a7 = reinterpret_cast<const uint2*>(xa + (size_t)sa_[ea + 7] * 64)[lane];
        float4 p0 = h4tof4(h2add(a0, a1));
        float4 p1 = h4tof4(h2add(a2, a3));
        float4 p2 = h4tof4(h2add(a4, a5));
        float4 p3 = h4tof4(h2add(a6, a7));
        sA = f4add(sA, f4add(f4add(p0, p1), f4add(p2, p3)));
    }
    for (; ea < ea1; ea++)
        sA = f4add(sA, h4tof4(reinterpret_cast<const uint2*>(xa + (size_t)sa_[ea] * 64)[lane]));
    for (; eb + 7 < eb1; eb += 8) {
        uint2 b0 = reinterpret_cast<const uint2*>(xb + (size_t)sb_[eb] * 64)[lane];
        uint2 b1 = reinterpret_cast<const uint2*>(xb + (size_t)sb_[eb + 1] * 64)[lane];
        uint2 b2 = reinterpret_cast<const uint2*>(xb + (size_t)sb_[eb + 2] * 64)[lane];
        uint2 b3 = reinterpret_cast<const uint2*>(xb + (size_t)sb_[eb + 3] * 64)[lane];
        uint2 b4 = reinterpret_cast<const uint2*>(xb + (size_t)sb_[eb + 4] * 64)[lane];
        uint2 b5 = reinterpret_cast<const uint2*>(xb + (size_t)sb_[eb + 5] * 64)[lane];
        uint2 b6 = reinterpret_cast<const uint2*>(xb + (size_t)sb_[eb + 6] * 64)[lane];
        uint2 b7 = reinterpret_cast<const uint2*>(xb + (size_t)sb_[eb + 7] * 64)[lane];
        float4 p0 = h4tof4(h2add(b0, b1));
        float4 p1 = h4tof4(h2add(b2, b3));
        float4 p2 = h4tof4(h2add(b4, b5));
        float4 p3 = h4tof4(h2add(b6, b7));
        sB = f4add(sB, f4add(f4add(p0, p1), f4add(p2, p3)));
    }
    for (; eb < eb1; eb++)
        sB = f4add(sB, h4tof4(reinterpret_cast<const uint2*>(xb + (size_t)sb_[eb] * 64)[lane]));

    float4 acc = f4add(reinterpret_cast<const float4*>(bias + r0 * 64)[lane],
                       reinterpret_cast<const float4*>(bias + r1 * 64)[lane]);
    acc = f4fma(sA, g_ininv[r0][n], acc);
    acc = f4fma(sB, g_ininv[r1][n], acc);
    reinterpret_cast<float4*>(g_node[t] + (size_t)n * 64)[lane] = acc;
    reinterpret_cast<uint2*>(g_nodeh[t] + (size_t)n * 64)[lane] =
        make_uint2(pack_h2(acc.x, acc.y), pack_h2(acc.z, acc.w));
}

// pre-GEMM agg (layer 3): relations {1,3}, dst rows [0,4096) only
__global__ void k_aggpre() {
    const int r = 1 + 2 * blockIdx.y;           // 1, 3
    const int n = blockIdx.x * blockDim.y + threadIdx.y;   // < 4096
    const int lane = threadIdx.x;     // 0..15
    const int smap[6] = {0, 1, 0, 2, 2, 1};
    const __half* x = g_nodeh[smap[r]];
    const float* oi = g_outinv[r];
    const int* srcs = g_srcs[r];
    int e0 = g_rowptr[r][n], e1 = g_rowptr[r][n + 1];
    float4 acc = make_float4(0.f, 0.f, 0.f, 0.f);
    int e = e0;
    for (; e + 7 < e1; e += 8) {
        int s0 = srcs[e], s1 = srcs[e + 1], s2 = srcs[e + 2], s3 = srcs[e + 3];
        int s4 = srcs[e + 4], s5 = srcs[e + 5], s6 = srcs[e + 6], s7 = srcs[e + 7];
        uint2 u0 = reinterpret_cast<const uint2*>(x + (size_t)s0 * 64)[lane];
        uint2 u1 = reinterpret_cast<const uint2*>(x + (size_t)s1 * 64)[lane];
        uint2 u2 = reinterpret_cast<const uint2*>(x + (size_t)s2 * 64)[lane];
        uint2 u3 = reinterpret_cast<const uint2*>(x + (size_t)s3 * 64)[lane];
        uint2 u4 = reinterpret_cast<const uint2*>(x + (size_t)s4 * 64)[lane];
        uint2 u5 = reinterpret_cast<const uint2*>(x + (size_t)s5 * 64)[lane];
        uint2 u6 = reinterpret_cast<const uint2*>(x + (size_t)s6 * 64)[lane];
        uint2 u7 = reinterpret_cast<const uint2*>(x + (size_t)s7 * 64)[lane];
        acc = f4fma(h4tof4(u0), oi[s0], acc);
        acc = f4fma(h4tof4(u1), oi[s1], acc);
        acc = f4fma(h4tof4(u2), oi[s2], acc);
        acc = f4fma(h4tof4(u3), oi[s3], acc);
        acc = f4fma(h4tof4(u4), oi[s4], acc);
        acc = f4fma(h4tof4(u5), oi[s5], acc);
        acc = f4fma(h4tof4(u6), oi[s6], acc);
        acc = f4fma(h4tof4(u7), oi[s7], acc);
    }
    for (; e < e1; e++) {
        int s0 = srcs[e];
        uint2 u0 = reinterpret_cast<const uint2*>(x + (size_t)s0 * 64)[lane];
        acc = f4fma(h4tof4(u0), oi[s0], acc);
    }
    reinterpret_cast<float4*>(g_agg[r] + (size_t)n * 64)[lane] = acc;
}

// ---------------- fused combine + L1-normalize (rows [0,4096)) -------------
__global__ void k_l1norm(const float* __restrict__ b3,
                         float* __restrict__ out, __half* __restrict__ feh) {
    int row = blockIdx.x;
    int h = threadIdx.x;  // 128
    float v = g_xs32[1][(size_t)row * OUTD + h] + g_xs32[3][(size_t)row * OUTD + h]
            + b3[128 + h] + b3[384 + h];
    float a = fabsf(v);
#pragma unroll
    for (int o = 16; o > 0; o >>= 1) a += __shfl_xor_sync(0xffffffffu, a, o);
    __shared__ float sh[4];
    if ((h & 31) == 0) sh[h >> 5] = a;
    __syncthreads();
    float tot = sh[0] + sh[1] + sh[2] + sh[3];
    float r = v / fmaxf(tot, 1e-12f);
    out[(size_t)row * OUTD + h] = r;
    feh[(size_t)row * OUTD + h] = __float2half_rn(r);
}

// ---------------- Adj fp32 -> fp16 -----------------------------------------
__global__ void k_cvt(const float4* __restrict__ src, __half* __restrict__ dst) {
    size_t i = (size_t)blockIdx.x * blockDim.x + threadIdx.x;
    float4 v = src[i];
    uint2 p = make_uint2(pack_h2(v.x, v.y), pack_h2(v.z, v.w));
    *reinterpret_cast<uint2*>(dst + 4 * i) = p;
}

// ---------------- weight transpose fp16: B[K][N] -> Bt[N][K] ---------------
__global__ void k_tsp(const float* __restrict__ B, __half* __restrict__ th,
                      int K, int N) {
    __shared__ float s[32][33];
    int n0 = blockIdx.x * 32, k0 = blockIdx.y * 32;
    int tx = threadIdx.x, ty = threadIdx.y;
#pragma unroll
    for (int i = 0; i < 32; i += 8)
        s[ty + i][tx] = B[(size_t)(k0 + ty + i) * N + n0 + tx];
    __syncthreads();
#pragma unroll
    for (int i = 0; i < 32; i += 8) {
        int n = n0 + ty + i, k = k0 + tx;
        th[(size_t)n * K + k] = __float2half_rn(s[tx][ty + i]);
    }
}

// ---------------- mma.sync + ldmatrix + cp.async plumbing ------------------
__device__ __forceinline__ uint32_t s2u(const void* p) {
    uint32_t a;
    asm("{ .reg .u64 t; cvta.to.shared.u64 t, %1; cvt.u32.u64 %0, t; }" : "=r"(a) : "l"(p));
    return a;
}
__device__ __forceinline__ void mma_f16(float* d, const uint32_t* a, const uint32_t* b) {
    asm volatile(
        "mma.sync.aligned.m16n8k16.row.col.f32.f16.f16.f32 "
        "{%0,%1,%2,%3}, {%4,%5,%6,%7}, {%8,%9}, {%0,%1,%2,%3};"
        : "+f"(d[0]), "+f"(d[1]), "+f"(d[2]), "+f"(d[3])
        : "r"(a[0]), "r"(a[1]), "r"(a[2]), "r"(a[3]), "r"(b[0]), "r"(b[1]));
}
__device__ __forceinline__ void ldsm4(uint32_t* r, uint32_t addr) {
    asm volatile("ldmatrix.sync.aligned.m8n8.x4.shared.b16 {%0,%1,%2,%3}, [%4];"
                 : "=r"(r[0]), "=r"(r[1]), "=r"(r[2]), "=r"(r[3]) : "r"(addr));
}
__device__ __forceinline__ void cpa16(uint32_t s, const void* g) {
    asm volatile("cp.async.cg.shared.global [%0], [%1], 16;" :: "r"(s), "l"(g));
}
#define CP_COMMIT() asm volatile("cp.async.commit_group;" ::: "memory")
#define CP_WAIT2()  asm volatile("cp.async.wait_group 2;" ::: "memory")

// ---------------- MLP GEMM: fp16 single-pass, templated BN -----------------
template <int ACT, int OUT, bool HC, int NT>
__global__ void __launch_bounds__(256, 1)
k_tc(const __half* __restrict__ A_, const __half* __restrict__ Bh_,
     const float* __restrict__ bias, const float* __restrict__ Cin,
     float* __restrict__ Cf, __half* __restrict__ Oh, int N, int K) {
    constexpr int BN = NT * 16;
    constexpr uint32_t ASZ = 16384u;
    constexpr uint32_t STG = ASZ + (uint32_t)BN * 128u;
    extern __shared__ char smc[];
    const uint32_t sb = s2u(smc);
    const int tid = threadIdx.x, lane = tid & 31, warp = tid >> 5;
    const int wm = warp & 3, wn = warp >> 2;
    const int g = lane >> 2, tig = lane & 3;
    const int bm = blockIdx.y * 128, bn = blockIdx.x * BN;

    float c[2][NT][4];
#pragma unroll
    for (int i = 0; i < 2; i++)
#pragma unroll
        for (int j = 0; j < NT; j++)
#pragma unroll
            for (int q = 0; q < 4; q++) c[i][j][q] = 0.f;

    auto load_stage = [&](int s) {
        const uint32_t st = sb + (uint32_t)(s % 3) * STG;
        const int k0 = s * 64;
#pragma unroll
        for (int j = 0; j < (128 + BN) / 32; j++) {
            int cidx = tid + 256 * j;
            int row = cidx >> 3, kc = cidx & 7;
            if (row < 128) {
                uint32_t off = (uint32_t)(row * 128 + kc * 16);
                off ^= (off >> 3) & 0x70;
                cpa16(st + off, A_ + (size_t)(bm + row) * K + k0 + kc * 8);
            } else {
                int br = row - 128;
                uint32_t off = (uint32_t)(br * 128 + kc * 16);
                off ^= (off >> 3) & 0x70;
                cpa16(st + ASZ + off, Bh_ + (size_t)(bn + br) * K + k0 + kc * 8);
            }
        }
    };

    const int nst = K >> 6;
#pragma unroll
    for (int i = 0; i < 3; i++) {
        if (i < nst) load_stage(i);
        CP_COMMIT();
    }

    for (int s = 0; s < nst; s++) {
        CP_WAIT2();
        __syncthreads();
        const uint32_t st = sb + (uint32_t)(s % 3) * STG;
#pragma unroll
        for (int kk = 0; kk < 64; kk += 16) {
            uint32_t ah[2][4], bh[NT][2];
#pragma unroll
            for (int mt = 0; mt < 2; mt++) {
                int row = wm * 32 + mt * 16 + (lane & 15);
                uint32_t off = (uint32_t)(row * 128) + (uint32_t)(kk * 2) + (uint32_t)(lane & 16);
                off ^= (off >> 3) & 0x70;
                ldsm4(ah[mt], st + off);
            }
#pragma unroll
            for (int bt = 0; bt < NT / 2; bt++) {
                int row = wn * (8 * NT) + bt * 16 + ((lane >> 4) << 3) + (lane & 7);
                uint32_t off = (uint32_t)(row * 128) + (uint32_t)(kk * 2) + (uint32_t)((lane & 8) << 1);
                off ^= (off >> 3) & 0x70;
                uint32_t r[4];
                ldsm4(r, st + ASZ + off);
                bh[2 * bt][0] = r[0]; bh[2 * bt][1] = r[1];
                bh[2 * bt + 1][0] = r[2]; bh[2 * bt + 1][1] = r[3];
            }
#pragma unroll
            for (int mt = 0; mt < 2; mt++)
#pragma unroll
                for (int nt = 0; nt < NT; nt++)
                    mma_f16(c[mt][nt], ah[mt], bh[nt]);
        }
        __syncthreads();
        if (s + 3 < nst) load_stage(s + 3);
        CP_COMMIT();
    }

    // epilogue
#pragma unroll
    for (int mt = 0; mt < 2; mt++) {
#pragma unroll
        for (int nt = 0; nt < NT; nt++) {
            int m0 = bm + wm * 32 + mt * 16 + g;
            int n0 = bn + wn * (8 * NT) + nt * 8 + 2 * tig;
            float2 v0 = make_float2(c[mt][nt][0], c[mt][nt][1]);
            float2 v1 = make_float2(c[mt][nt][2], c[mt][nt][3]);
            if (HC) {
                float2 ci0 = *reinterpret_cast<const float2*>(Cin + (size_t)m0 * N + n0);
                float2 ci1 = *reinterpret_cast<const float2*>(Cin + (size_t)(m0 + 8) * N + n0);
                v0.x += ci0.x; v0.y += ci0.y; v1.x += ci1.x; v1.y += ci1.y;
            }
            if (bias) {
                float bx = bias[n0], by = bias[n0 + 1];
                v0.x += bx; v0.y += by; v1.x += bx; v1.y += by;
            }
            if (ACT == 1) {
                v0.x = fmaxf(v0.x, 0.f); v0.y = fmaxf(v0.y, 0.f);
                v1.x = fmaxf(v1.x, 0.f); v1.y = fmaxf(v1.y, 0.f);
            } else if (ACT == 2) {
                v0.x = 1.f / (1.f + __expf(-v0.x)); v0.y = 1.f / (1.f + __expf(-v0.y));
                v1.x = 1.f / (1.f + __expf(-v1.x)); v1.y = 1.f / (1.f + __expf(-v1.y));
            }
            if (OUT == 0) {
                *reinterpret_cast<float2*>(Cf + (size_t)m0 * N + n0) = v0;
                *reinterpret_cast<float2*>(Cf + (size_t)(m0 + 8) * N + n0) = v1;
            } else {
                *reinterpret_cast<uint32_t*>(Oh + (size_t)m0 * N + n0) = pack_h2(v0.x, v0.y);
                *reinterpret_cast<uint32_t*>(Oh + (size_t)(m0 + 8) * N + n0) = pack_h2(v1.x, v1.y);
            }
        }
    }
}

#define SM8  (3 * (16384 + 128 * 128))   // 96 KB  (NT=8)
#define SM16 (3 * (16384 + 256 * 128))   // 144 KB (NT=16)

// ---------------- orchestration ----------------
extern "C" void kernel_launch(void* const* d_in, const int* in_sizes, int n_in,
                              void* d_out, int out_size) {
    const float* hM  = (const float*)d_in[0];
    const float* hD  = (const float*)d_in[1];
    const float* hT  = (const float*)d_in[2];
    const float* W1  = (const float*)d_in[3];
    const float* b1  = (const float*)d_in[4];
    const float* W2  = (const float*)d_in[5];
    const float* b2  = (const float*)d_in[6];
    const float* W3  = (const float*)d_in[7];
    const float* b3  = (const float*)d_in[8];
    const float* Adj = (const float*)d_in[9];
    const float* f1w = (const float*)d_in[10];
    const float* f1b = (const float*)d_in[11];
    const float* f2w = (const float*)d_in[12];
    const float* f2b = (const float*)d_in[13];
    const float* f3w = (const float*)d_in[14];
    const float* f3b = (const float*)d_in[15];
    const float* f4w = (const float*)d_in[16];
    const float* f4b = (const float*)d_in[17];
    const int* edges = (const int*)d_in[18];

    float *p_node, *p_agg, *p_outinv, *p_ininv, *p_xs32, *p_x1f;
    __half *p_bth, *p_adjh, *p_feh, *p_x1h, *p_x2h, *p_x3h, *p_xsh;
    cudaGetSymbolAddress((void**)&p_node, g_node);
    cudaGetSymbolAddress((void**)&p_agg, g_agg);
    cudaGetSymbolAddress((void**)&p_outinv, g_outinv);
    cudaGetSymbolAddress((void**)&p_ininv, g_ininv);
    cudaGetSymbolAddress((void**)&p_xs32, g_xs32);
    cudaGetSymbolAddress((void**)&p_xsh, g_xsh);
    cudaGetSymbolAddress((void**)&p_bth, g_bth);
    cudaGetSymbolAddress((void**)&p_adjh, g_adjh);
    cudaGetSymbolAddress((void**)&p_feh, g_feh);
    cudaGetSymbolAddress((void**)&p_x1f, g_x1f);
    cudaGetSymbolAddress((void**)&p_x1h, g_x1h);
    cudaGetSymbolAddress((void**)&p_x2h, g_x2h);
    cudaGetSymbolAddress((void**)&p_x3h, g_x3h);

    float* fe   = (float*)d_out;                       // 4096 x 128
    float* outx = (float*)d_out + (size_t)MROW * OUTD; // 4096 x 8192

    static cudaStream_t s2 = nullptr, s3 = nullptr;
    static cudaEvent_t evFork = nullptr, evJoin = nullptr, evScan = nullptr, evFill = nullptr;
    if (s2 == nullptr) {
        cudaStreamCreateWithFlags(&s2, cudaStreamNonBlocking);
        cudaStreamCreateWithFlags(&s3, cudaStreamNonBlocking);
        cudaEventCreateWithFlags(&evFork, cudaEventDisableTiming);
        cudaEventCreateWithFlags(&evJoin, cudaEventDisableTiming);
        cudaEventCreateWithFlags(&evScan, cudaEventDisableTiming);
        cudaEventCreateWithFlags(&evFill, cudaEventDisableTiming);
        cudaFuncSetAttribute(k_tc<0, 0, false, 8>, cudaFuncAttributeMaxDynamicSharedMemorySize, SM8);
        cudaFuncSetAttribute(k_tc<1, 1, true, 8>,  cudaFuncAttributeMaxDynamicSharedMemorySize, SM8);
        cudaFuncSetAttribute(k_tc<1, 1, false, 8>, cudaFuncAttributeMaxDynamicSharedMemorySize, SM8);
        cudaFuncSetAttribute(k_tc<2, 0, false, 16>, cudaFuncAttributeMaxDynamicSharedMemorySize, SM16);
        cudaFuncSetAttribute(k_count, cudaFuncAttributeMaxDynamicSharedMemorySize, 2 * NN * 4);
    }

    // ---- fork s2: MLP prep + Adj GEMM (independent of GNN) ----
    cudaEventRecord(evFork, 0);
    cudaStreamWaitEvent(s2, evFork, 0);
    k_cvt<<<(MROW * ITEM / 4) / 256, 256, 0, s2>>>((const float4*)Adj, p_adjh);
    k_tsp<<<dim3(256 / 32, 8192 / 32), dim3(32, 8), 0, s2>>>(f1w, p_bth + O1A, 8192, 256);
    k_tsp<<<dim3(256 / 32, 128 / 32),  dim3(32, 8), 0, s2>>>(f1w + (size_t)ITEM * 256, p_bth + O1B, 128, 256);
    k_tsp<<<dim3(512 / 32, 256 / 32),  dim3(32, 8), 0, s2>>>(f2w, p_bth + O2, 256, 512);
    k_tsp<<<dim3(1024 / 32, 512 / 32), dim3(32, 8), 0, s2>>>(f3w, p_bth + O3, 512, 1024);
    k_tsp<<<dim3(8192 / 32, 1024 / 32), dim3(32, 8), 0, s2>>>(f4w, p_bth + O4, 1024, 8192);
    k_tc<0, 0, false, 8><<<dim3(2, 32), 256, SM8, s2>>>(
        p_adjh, p_bth + O1A, nullptr, nullptr, p_x1f, nullptr, 256, 8192);
    cudaEventRecord(evJoin, s2);

    // ---- main stream: CSR counts + scan ----
    k_zero_counts<<<(NREL * NN + 255) / 256, 256>>>();
    k_count<<<dim3(CB, NREL), 512, 2 * NN * 4>>>(edges);
    k_scan<<<NREL, 1024>>>();
    cudaEventRecord(evScan, 0);

    // ---- fork s3: CSR fill (privatized two-phase) ----
    cudaStreamWaitEvent(s3, evScan, 0);
    k_fill<<<dim3(CB, NREL), 512, 0, s3>>>(edges);
    cudaEventRecord(evFill, s3);

    // ---- main: layer-1 conv overlaps fill ----
    k_conv_b<__half><<<dim3(1, NN / 64, 6), 256>>>(hM, hD, hT, W1, p_outinv, 256, 64,
                                                   p_xsh, (size_t)NN * 64, 0x543210u);
    cudaStreamWaitEvent(0, evFill, 0);
    k_agg_v<<<dim3(NN / 16, 3), dim3(16, 16)>>>(b1, 0);

    // layer 2: relations {0,2,4,5}, targets {D,T}
    k_conv_b<__half><<<dim3(1, NN / 64, 4), 256>>>(p_node, p_node + (size_t)NN * 128,
                                                   p_node + (size_t)2 * NN * 128, W2,
                                                   p_outinv, 64, 64, p_xsh, (size_t)NN * 64,
                                                   0x5420u);
    k_agg_v<<<dim3(NN / 16, 2), dim3(16, 16)>>>(b2, 1);

    // layer 3: relations {1,3}, dst rows [0,4096) only
    k_aggpre<<<dim3(MROW / 16, 2), dim3(16, 16)>>>();
    k_conv_b<float><<<dim3(2, MROW / 64, 2), 256>>>(p_agg, nullptr, nullptr, W3, p_ininv,
                                                    64, 128, p_xs32, (size_t)NN * 128, 0x31u);
    k_l1norm<<<MROW, 128>>>(b3, fe, p_feh);

    // ---- join + MLP tail ----
    cudaStreamWaitEvent(0, evJoin, 0);

    k_tc<1, 1, true, 8><<<dim3(2, 32), 256, SM8>>>(
        p_feh, p_bth + O1B, f1b, p_x1f, nullptr, p_x1h, 256, 128);
    k_tc<1, 1, false, 8><<<dim3(4, 32), 256, SM8>>>(
        p_x1h, p_bth + O2, f2b, nullptr, nullptr, p_x2h, 512, 256);
    k_tc<1, 1, false, 8><<<dim3(8, 32), 256, SM8>>>(
        p_x2h, p_bth + O3, f3b, nullptr, nullptr, p_x3h, 1024, 512);
    k_tc<2, 0, false, 16><<<dim3(32, 32), 256, SM16>>>(
        p_x3h, p_bth + O4, f4b, nullptr, outx, nullptr, 8192, 1024);
}